// round 1
// baseline (speedup 1.0000x reference)
#include <cuda_runtime.h>

// ---------------------------------------------------------------------------
// Problem constants
// ---------------------------------------------------------------------------
namespace {
constexpr int kT = 2048;
constexpr int kS = 512;
constexpr int kB = 16;
constexpr int kA = 18;
constexpr int kColsTot = kB * kA + kB * 2 + kB;  // 288 + 32 + 16 = 336
constexpr int kRowsPerBlk = 16;
}
#define EXP_NEG_PEN 0.60653065971263342f /* exp(-0.5) */

// Scratch (device globals: no allocation allowed). (T+1) x B each, fp32.
__device__ float g_es0[(kT + 1) * kB];   // exp(log_softmax(stop)[...,0])
__device__ float g_es1[(kT + 1) * kB];   // exp(log_softmax(stop)[...,1])
__device__ float g_est[(kT + 1) * kB];   // softmax over b of start logits
__device__ float g_eac[kT * kB];         // exp(log_softmax(action)[i,b,actions[i]])

// ---------------------------------------------------------------------------
// Kernel 1: fused GEMM (2049 x 336, K=512) + softmax epilogues.
// One block handles 16 rows of s_i; all 336 columns; W streamed from L2.
// ---------------------------------------------------------------------------
__device__ __forceinline__ void compute_col(const float* __restrict__ base,
                                            int stride, int off,
                                            const float4* __restrict__ s4,
                                            float acc[kRowsPerBlk]) {
#pragma unroll
    for (int r = 0; r < kRowsPerBlk; r++) acc[r] = 0.0f;
    for (int k = 0; k < kS; k += 4) {
        float w0 = base[(k + 0) * stride + off];
        float w1 = base[(k + 1) * stride + off];
        float w2 = base[(k + 2) * stride + off];
        float w3 = base[(k + 3) * stride + off];
#pragma unroll
        for (int r = 0; r < kRowsPerBlk; r++) {
            float4 sv = s4[r * (kS / 4) + (k >> 2)];
            acc[r] = fmaf(sv.x, w0, fmaf(sv.y, w1, fmaf(sv.z, w2, fmaf(sv.w, w3, acc[r]))));
        }
    }
}

__global__ __launch_bounds__(256) void prep_kernel(
    const float* __restrict__ s_i,
    const float* __restrict__ Wa,    // (512, 288)
    const float* __restrict__ Wsp,   // (512, 32)
    const float* __restrict__ Wst,   // (512, 16)
    const void* __restrict__ actions_raw) {
    __shared__ __align__(16) float sm[kRowsPerBlk * kS];  // 32 KB; reused for logits
    __shared__ int s_is64;

    const int tid  = threadIdx.x;
    const int row0 = blockIdx.x * kRowsPerBlk;

    // Detect actions dtype (int64 vs int32): values are in [0,18), so if the
    // buffer is little-endian int64 every odd 32-bit word is 0.
    if (tid == 0) {
        const unsigned* w = (const unsigned*)actions_raw;
        unsigned acc = 0;
#pragma unroll
        for (int j = 1; j < 64; j += 2) acc |= w[j];
        s_is64 = (acc == 0u) ? 1 : 0;
    }

    // Phase A: stage s_i rows into smem (zero-fill out-of-range rows).
    for (int idx = tid; idx < kRowsPerBlk * kS; idx += 256) {
        int r = idx >> 9;          // / 512
        int k = idx & (kS - 1);
        int gr = row0 + r;
        sm[idx] = (gr <= kT) ? s_i[gr * kS + k] : 0.0f;
    }
    __syncthreads();

    // Phase B: each thread computes 1-2 columns (col = tid, tid+256).
    float accA[kRowsPerBlk];
    float accB[kRowsPerBlk];
    const float4* s4 = (const float4*)sm;
    {
        int c = tid;  // 0..255 < 336 always
        const float* base; int stride, off;
        if (c < 288)      { base = Wa;  stride = 288; off = c; }
        else if (c < 320) { base = Wsp; stride = 32;  off = c - 288; }
        else              { base = Wst; stride = 16;  off = c - 320; }
        compute_col(base, stride, off, s4, accA);
    }
    const int c1 = tid + 256;
    if (c1 < kColsTot) {  // tid < 80
        const float* base; int stride, off;
        if (c1 < 288)      { base = Wa;  stride = 288; off = c1; }
        else if (c1 < 320) { base = Wsp; stride = 32;  off = c1 - 288; }
        else               { base = Wst; stride = 16;  off = c1 - 320; }
        compute_col(base, stride, off, s4, accB);
    }
    __syncthreads();  // all reads of s done

    // Phase C: scatter logits into smem (row stride 512, cols 0..335).
#pragma unroll
    for (int r = 0; r < kRowsPerBlk; r++) sm[r * kS + tid] = accA[r];
    if (c1 < kColsTot) {
#pragma unroll
        for (int r = 0; r < kRowsPerBlk; r++) sm[r * kS + c1] = accB[r];
    }
    __syncthreads();

    // Phase D: softmaxes. One thread per (row, b): tid = r*16 + b.
    const int r = tid >> 4;
    const int b = tid & 15;
    const int i = row0 + r;
    const bool valid = (i <= kT);
    const int is64 = s_is64;

    if (valid) {
        // action log-softmax over A=18, keep only selected action
        if (i < kT) {
            int a;
            if (is64) a = (int)((const long long*)actions_raw)[i];
            else      a = ((const int*)actions_raw)[i];
            const float* L = &sm[r * kS + b * kA];
            float m = L[0];
#pragma unroll
            for (int j = 1; j < kA; j++) m = fmaxf(m, L[j]);
            float s = 0.0f;
#pragma unroll
            for (int j = 0; j < kA; j++) s += expf(L[j] - m);
            g_eac[i * kB + b] = expf(L[a] - m) / s;
        }
        // stop softmax over 2
        float x0 = sm[r * kS + 288 + 2 * b];
        float x1 = sm[r * kS + 288 + 2 * b + 1];
        float m = fmaxf(x0, x1);
        float e0 = expf(x0 - m), e1 = expf(x1 - m);
        float inv = 1.0f / (e0 + e1);
        g_es0[i * kB + b] = e0 * inv;
        g_es1[i * kB + b] = e1 * inv;
    }
    // start softmax over b (16 lanes per row; warp holds 2 rows -> xor<=8 stays
    // inside each 16-lane half). Invalid rows hold 0-logits: harmless.
    {
        float x = sm[r * kS + 320 + b];
        float m = x;
        m = fmaxf(m, __shfl_xor_sync(0xFFFFFFFFu, m, 1));
        m = fmaxf(m, __shfl_xor_sync(0xFFFFFFFFu, m, 2));
        m = fmaxf(m, __shfl_xor_sync(0xFFFFFFFFu, m, 4));
        m = fmaxf(m, __shfl_xor_sync(0xFFFFFFFFu, m, 8));
        float e = expf(x - m);
        float s = e;
        s += __shfl_xor_sync(0xFFFFFFFFu, s, 1);
        s += __shfl_xor_sync(0xFFFFFFFFu, s, 2);
        s += __shfl_xor_sync(0xFFFFFFFFu, s, 4);
        s += __shfl_xor_sync(0xFFFFFFFFu, s, 8);
        if (valid) g_est[i * kB + b] = e / s;
    }
}

// ---------------------------------------------------------------------------
// Kernel 2: sequential exp-space scan, 1 warp, b = lane&15 (duplicated halves).
//   Q_i[b] = Q_{i-1}[b]*es0[i,b] + est[i,b]*exp(-PEN)*(sum_b Q_{i-1}*es1[i,b])
//   tot   += log(sum_b Q_i[b]*eac[i,b]) + Lambda
// ---------------------------------------------------------------------------
__device__ __forceinline__ float bfly_sum(float v) {
    v += __shfl_xor_sync(0xFFFFFFFFu, v, 1);
    v += __shfl_xor_sync(0xFFFFFFFFu, v, 2);
    v += __shfl_xor_sync(0xFFFFFFFFu, v, 4);
    v += __shfl_xor_sync(0xFFFFFFFFu, v, 8);
    return v;
}

__global__ __launch_bounds__(32) void scan_kernel(float* __restrict__ out) {
    const int lane = threadIdx.x;
    const int b = lane & 15;

    float Q = g_est[b];          // buf0 row 0 = start_logps[0]
    float Lam = 0.0f;
    double tot;
    {   // step 0: tot += logsumexp_b(act[0,b] + start[0,b])
        float u = bfly_sum(Q * g_eac[b]);
        tot = (double)__logf(u);
    }

    // Software prefetch, distance 4 (L2 latency ~250 cyc < 4 * step chain).
    constexpr int PF = 4;
    float pf0[PF], pf1[PF], pfs[PF], pfa[PF];
#pragma unroll
    for (int j = 0; j < PF; j++) {
        int i = 1 + j;
        pf0[j] = g_es0[i * kB + b];
        pf1[j] = g_es1[i * kB + b];
        pfs[j] = g_est[i * kB + b];
        pfa[j] = g_eac[i * kB + b];
    }

#pragma unroll 4
    for (int i = 1; i < kT; i++) {
        const int slot = (i - 1) & (PF - 1);
        float s0 = pf0[slot], s1 = pf1[slot], st = pfs[slot], ea = pfa[slot];
        int ip = i + PF;
        if (ip < kT) {
            pf0[slot] = g_es0[ip * kB + b];
            pf1[slot] = g_es1[ip * kB + b];
            pfs[slot] = g_est[ip * kB + b];
            pfa[slot] = g_eac[ip * kB + b];
        }
        // critical chain: mul -> 4x shuffle-add -> fma
        float t = bfly_sum(Q * s1);
        Q = fmaf(Q, s0, (st * EXP_NEG_PEN) * t);
        // tot contribution (off the Q-chain)
        float u = bfly_sum(Q * ea);
        tot += (double)(__logf(u) + Lam);
        // periodic renormalization (uniform branch)
        if ((i & 15) == 0) {
            float ssum = bfly_sum(Q);
            Q *= (1.0f / ssum);
            Lam += __logf(ssum);
        }
    }

    // final: tot += logsumexp_b over buf of (stop_logps[T,b,0] + buf)
    {
        float u = bfly_sum(Q * g_es0[kT * kB + b]);
        tot += (double)(__logf(u) + Lam);
    }
    if (lane == 0) out[0] = (float)tot;
}

// ---------------------------------------------------------------------------
// Launch
// ---------------------------------------------------------------------------
extern "C" void kernel_launch(void* const* d_in, const int* in_sizes, int n_in,
                              void* d_out, int out_size) {
    const float* s_i = (const float*)d_in[0];
    const float* Wa  = (const float*)d_in[1];
    const float* Wsp = (const float*)d_in[2];
    const float* Wst = (const float*)d_in[3];
    const void*  act = d_in[4];

    const int nblk = (kT + 1 + kRowsPerBlk - 1) / kRowsPerBlk;  // 129
    prep_kernel<<<nblk, 256>>>(s_i, Wa, Wsp, Wst, act);
    scan_kernel<<<1, 32>>>((float*)d_out);
}

// round 3
// speedup vs baseline: 4.2162x; 4.2162x over previous
#include <cuda_runtime.h>

// ---------------------------------------------------------------------------
// Problem constants
// ---------------------------------------------------------------------------
namespace {
constexpr int kT = 2048;
constexpr int kS = 512;
constexpr int kB = 16;
constexpr int kA = 18;
constexpr int kColsTot = kB * kA + kB * 2 + kB;  // 336
constexpr int kRowsPerBlk = 16;
constexpr int kBlkSteps = 16;          // steps composed per block matrix
constexpr int kNBlks = kT / kBlkSteps; // 128
}
#define EXP_NEG_PEN 0.60653065971263342f /* exp(-0.5) */
#define LN2 0.69314718055994530942

// Scratch (device globals). Natural layout [i*16 + b].
__device__ float g_es0[(kT + 1) * kB];
__device__ float g_es1[(kT + 1) * kB];
__device__ float g_est[(kT + 1) * kB];
__device__ float g_eac[kT * kB];
__device__ float g_M[kNBlks * kB * kB];   // g_M[blk*256 + row*16 + col]
__device__ float g_chk[(kNBlks + 1) * kB]; // normalized state before block j
__device__ int   g_Eb[kNBlks + 1];         // power-of-2 exponent of chk
__device__ double g_part[kNBlks];          // per-block partial log sums

// ---------------------------------------------------------------------------
// Kernel 1: fused GEMM (2049 x 336, K=512) + softmax epilogues. (unchanged)
// ---------------------------------------------------------------------------
__device__ __forceinline__ void compute_col(const float* __restrict__ base,
                                            int stride, int off,
                                            const float4* __restrict__ s4,
                                            float acc[kRowsPerBlk]) {
#pragma unroll
    for (int r = 0; r < kRowsPerBlk; r++) acc[r] = 0.0f;
    for (int k = 0; k < kS; k += 4) {
        float w0 = base[(k + 0) * stride + off];
        float w1 = base[(k + 1) * stride + off];
        float w2 = base[(k + 2) * stride + off];
        float w3 = base[(k + 3) * stride + off];
#pragma unroll
        for (int r = 0; r < kRowsPerBlk; r++) {
            float4 sv = s4[r * (kS / 4) + (k >> 2)];
            acc[r] = fmaf(sv.x, w0, fmaf(sv.y, w1, fmaf(sv.z, w2, fmaf(sv.w, w3, acc[r]))));
        }
    }
}

__global__ __launch_bounds__(256) void prep_kernel(
    const float* __restrict__ s_i,
    const float* __restrict__ Wa,
    const float* __restrict__ Wsp,
    const float* __restrict__ Wst,
    const void* __restrict__ actions_raw) {
    __shared__ __align__(16) float sm[kRowsPerBlk * kS];
    __shared__ int s_is64;

    const int tid  = threadIdx.x;
    const int row0 = blockIdx.x * kRowsPerBlk;

    if (tid == 0) {
        const unsigned* w = (const unsigned*)actions_raw;
        unsigned acc = 0;
#pragma unroll
        for (int j = 1; j < 64; j += 2) acc |= w[j];
        s_is64 = (acc == 0u) ? 1 : 0;
    }

    for (int idx = tid; idx < kRowsPerBlk * kS; idx += 256) {
        int r = idx >> 9;
        int k = idx & (kS - 1);
        int gr = row0 + r;
        sm[idx] = (gr <= kT) ? s_i[gr * kS + k] : 0.0f;
    }
    __syncthreads();

    float accA[kRowsPerBlk];
    float accB[kRowsPerBlk];
    const float4* s4 = (const float4*)sm;
    {
        int c = tid;
        const float* base; int stride, off;
        if (c < 288)      { base = Wa;  stride = 288; off = c; }
        else if (c < 320) { base = Wsp; stride = 32;  off = c - 288; }
        else              { base = Wst; stride = 16;  off = c - 320; }
        compute_col(base, stride, off, s4, accA);
    }
    const int c1 = tid + 256;
    if (c1 < kColsTot) {
        const float* base; int stride, off;
        if (c1 < 288)      { base = Wa;  stride = 288; off = c1; }
        else if (c1 < 320) { base = Wsp; stride = 32;  off = c1 - 288; }
        else               { base = Wst; stride = 16;  off = c1 - 320; }
        compute_col(base, stride, off, s4, accB);
    }
    __syncthreads();

#pragma unroll
    for (int r = 0; r < kRowsPerBlk; r++) sm[r * kS + tid] = accA[r];
    if (c1 < kColsTot) {
#pragma unroll
        for (int r = 0; r < kRowsPerBlk; r++) sm[r * kS + c1] = accB[r];
    }
    __syncthreads();

    const int r = tid >> 4;
    const int b = tid & 15;
    const int i = row0 + r;
    const bool valid = (i <= kT);
    const int is64 = s_is64;

    if (valid) {
        if (i < kT) {
            int a;
            if (is64) a = (int)((const long long*)actions_raw)[i];
            else      a = ((const int*)actions_raw)[i];
            const float* L = &sm[r * kS + b * kA];
            float m = L[0];
#pragma unroll
            for (int j = 1; j < kA; j++) m = fmaxf(m, L[j]);
            float s = 0.0f;
#pragma unroll
            for (int j = 0; j < kA; j++) s += expf(L[j] - m);
            g_eac[i * kB + b] = expf(L[a] - m) / s;
        }
        float x0 = sm[r * kS + 288 + 2 * b];
        float x1 = sm[r * kS + 288 + 2 * b + 1];
        float m = fmaxf(x0, x1);
        float e0 = expf(x0 - m), e1 = expf(x1 - m);
        float inv = 1.0f / (e0 + e1);
        g_es0[i * kB + b] = e0 * inv;
        g_es1[i * kB + b] = e1 * inv;
    }
    {
        float x = sm[r * kS + 320 + b];
        float m = x;
        m = fmaxf(m, __shfl_xor_sync(0xFFFFFFFFu, m, 1));
        m = fmaxf(m, __shfl_xor_sync(0xFFFFFFFFu, m, 2));
        m = fmaxf(m, __shfl_xor_sync(0xFFFFFFFFu, m, 4));
        m = fmaxf(m, __shfl_xor_sync(0xFFFFFFFFu, m, 8));
        float e = expf(x - m);
        float s = e;
        s += __shfl_xor_sync(0xFFFFFFFFu, s, 1);
        s += __shfl_xor_sync(0xFFFFFFFFu, s, 2);
        s += __shfl_xor_sync(0xFFFFFFFFu, s, 4);
        s += __shfl_xor_sync(0xFFFFFFFFu, s, 8);
        if (valid) g_est[i * kB + b] = e / s;
    }
}

// ---------------------------------------------------------------------------
// helpers
// ---------------------------------------------------------------------------
__device__ __forceinline__ void load16(float d[16], const float* __restrict__ p) {
    const float4* p4 = (const float4*)p;
    float4 a = p4[0], b = p4[1], c = p4[2], e = p4[3];
    d[0]=a.x; d[1]=a.y; d[2]=a.z; d[3]=a.w;
    d[4]=b.x; d[5]=b.y; d[6]=b.z; d[7]=b.w;
    d[8]=c.x; d[9]=c.y; d[10]=c.z; d[11]=c.w;
    d[12]=e.x; d[13]=e.y; d[14]=e.z; d[15]=e.w;
}
__device__ __forceinline__ float tree16(const float v[16]) {
    float a0=v[0]+v[1], a1=v[2]+v[3], a2=v[4]+v[5], a3=v[6]+v[7];
    float a4=v[8]+v[9], a5=v[10]+v[11], a6=v[12]+v[13], a7=v[14]+v[15];
    float b0=a0+a1, b1=a2+a3, b2=a4+a5, b3=a6+a7;
    return (b0+b1)+(b2+b3);
}
__device__ __forceinline__ float bfly16(float v) {
    v += __shfl_xor_sync(0xFFFFFFFFu, v, 1);
    v += __shfl_xor_sync(0xFFFFFFFFu, v, 2);
    v += __shfl_xor_sync(0xFFFFFFFFu, v, 4);
    v += __shfl_xor_sync(0xFFFFFFFFu, v, 8);
    return v;
}

// ---------------------------------------------------------------------------
// Kernel 2: compose 16 step-maps into one dense 16x16 matrix per block.
// One warp per block; lane k (mod 16) holds column k of P. P starts as I.
//   step: w_k = s1 . P[:,k];  P[j,k] = s0[j]*P[j,k] + v[j]*w_k
// Stores transposed (row-major rows) for the serial kernel's row loads.
// ---------------------------------------------------------------------------
__global__ __launch_bounds__(32) void compose_kernel() {
    const int blk = blockIdx.x;
    const int lane = threadIdx.x;
    const int k = lane & 15;

    float P[16];
#pragma unroll
    for (int j = 0; j < 16; j++) P[j] = (j == k) ? 1.0f : 0.0f;

    for (int s = 0; s < kBlkSteps; s++) {
        int i = blk * kBlkSteps + s;
        if (i == 0) continue;  // step 0 leaves buf unchanged
        float s0[16], s1[16], vv[16];
        load16(s0, &g_es0[i * kB]);
        load16(s1, &g_es1[i * kB]);
        load16(vv, &g_est[i * kB]);
        float m[16];
#pragma unroll
        for (int j = 0; j < 16; j++) m[j] = s1[j] * P[j];
        float w = tree16(m);
#pragma unroll
        for (int j = 0; j < 16; j++)
            P[j] = fmaf(s0[j], P[j], (vv[j] * EXP_NEG_PEN) * w);
    }

    if (lane < 16) {
#pragma unroll
        for (int j = 0; j < 16; j++)
            g_M[blk * 256 + j * 16 + k] = P[j];
    }
}

// ---------------------------------------------------------------------------
// Kernel 3: serial scan over 128 block matrices. One warp.
// Replicated Q: every lane holds the full 16-vector. Lane r (mod 16) owns
// row r of M_blk: out_r = dot(Mrow_r, Q) (local tree, no cross-lane).
// Then 16 independent broadcast shuffles rebuild replicated Q (latencies
// overlap). Power-of-2 renorm per block step; checkpoints stored for replay.
// ---------------------------------------------------------------------------
__global__ __launch_bounds__(32) void serial_kernel() {
    const int lane = threadIdx.x;
    const int r = lane & 15;

    float Q[16];
    load16(Q, &g_est[0]);           // Q_init, replicated in every lane
    if (lane < 16) g_chk[lane] = Q[lane];
    if (lane == 0) g_Eb[0] = 0;
    int E = 0;

    // prefetch rows of M for j=0
    float4 m0, m1, m2, m3;
    {
        const float4* Mr = (const float4*)&g_M[r * 16];
        m0 = Mr[0]; m1 = Mr[1]; m2 = Mr[2]; m3 = Mr[3];
    }

    for (int j = 0; j < kNBlks; j++) {
        float4 n0, n1, n2, n3;
        if (j + 1 < kNBlks) {
            const float4* Mn = (const float4*)&g_M[(j + 1) * 256 + r * 16];
            n0 = Mn[0]; n1 = Mn[1]; n2 = Mn[2]; n3 = Mn[3];
        }
        float mm[16] = {m0.x, m0.y, m0.z, m0.w, m1.x, m1.y, m1.z, m1.w,
                        m2.x, m2.y, m2.z, m2.w, m3.x, m3.y, m3.z, m3.w};
        float pr[16];
#pragma unroll
        for (int kk = 0; kk < 16; kk++) pr[kk] = mm[kk] * Q[kk];
        float outr = tree16(pr);

        // 16 independent broadcasts: Qn[k] = out of lane k
        float Qn[16];
#pragma unroll
        for (int kk = 0; kk < 16; kk++)
            Qn[kk] = __shfl_sync(0xFFFFFFFFu, outr, kk);

        // uniform power-of-2 renorm from sum (all lanes compute identically)
        float ss = tree16(Qn);
        int e = ((__float_as_int(ss) >> 23) & 0xFF) - 127;
        float sc = __int_as_float((127 - e) << 23);
#pragma unroll
        for (int kk = 0; kk < 16; kk++) Q[kk] = Qn[kk] * sc;
        E += e;

        if (lane < 16) g_chk[(j + 1) * kB + lane] = Q[lane];
        if (lane == 0) g_Eb[j + 1] = E;

        m0 = n0; m1 = n1; m2 = n2; m3 = n3;
    }
}

// ---------------------------------------------------------------------------
// Kernel 4: parallel replay. Warp j re-runs steps [16j, 16j+16) from the
// checkpoint, computing u_i = sum_b Q_i[b]*eac[i,b] and accumulating log.
// Block 127 also adds the final stop term.
// ---------------------------------------------------------------------------
__global__ __launch_bounds__(32) void replay_kernel() {
    const int blk = blockIdx.x;
    const int lane = threadIdx.x;
    const int b = lane & 15;

    float Q = g_chk[blk * kB + b];
    const int E = g_Eb[blk];
    double acc = 0.0;

    for (int s = 0; s < kBlkSteps; s++) {
        int i = blk * kBlkSteps + s;
        int idx = i * kB + b;
        float s0 = g_es0[idx];
        float s1 = g_es1[idx];
        float v  = g_est[idx] * EXP_NEG_PEN;
        float ea = g_eac[idx];
        if (i > 0) {
            float t = bfly16(Q * s1);
            Q = fmaf(v, t, Q * s0);
        }
        float u = bfly16(Q * ea);
        acc += (double)logf(u);
    }
    acc += (double)(kBlkSteps * E) * LN2;

    if (blk == kNBlks - 1) {
        float u = bfly16(Q * g_es0[kT * kB + b]);
        acc += (double)logf(u) + (double)E * LN2;
    }
    if (lane == 0) g_part[blk] = acc;
}

// ---------------------------------------------------------------------------
// Kernel 5: deterministic fixed-tree reduction of 128 doubles.
// ---------------------------------------------------------------------------
__global__ __launch_bounds__(128) void reduce_kernel(float* __restrict__ out) {
    __shared__ double red[128];
    const int tid = threadIdx.x;
    red[tid] = g_part[tid];
    __syncthreads();
#pragma unroll
    for (int s = 64; s > 0; s >>= 1) {
        if (tid < s) red[tid] += red[tid + s];
        __syncthreads();
    }
    if (tid == 0) out[0] = (float)red[0];
}

// ---------------------------------------------------------------------------
// Launch
// ---------------------------------------------------------------------------
extern "C" void kernel_launch(void* const* d_in, const int* in_sizes, int n_in,
                              void* d_out, int out_size) {
    const float* s_i = (const float*)d_in[0];
    const float* Wa  = (const float*)d_in[1];
    const float* Wsp = (const float*)d_in[2];
    const float* Wst = (const float*)d_in[3];
    const void*  act = d_in[4];

    const int nblk = (kT + 1 + kRowsPerBlk - 1) / kRowsPerBlk;  // 129
    prep_kernel<<<nblk, 256>>>(s_i, Wa, Wsp, Wst, act);
    compose_kernel<<<kNBlks, 32>>>();
    serial_kernel<<<1, 32>>>();
    replay_kernel<<<kNBlks, 32>>>();
    reduce_kernel<<<1, 128>>>((float*)d_out);
}

// round 4
// speedup vs baseline: 4.5673x; 1.0833x over previous
#include <cuda_runtime.h>

// ---------------------------------------------------------------------------
// Problem constants
// ---------------------------------------------------------------------------
namespace {
constexpr int kT = 2048;
constexpr int kS = 512;
constexpr int kB = 16;
constexpr int kA = 18;
constexpr int kColsTot = kB * kA + kB * 2 + kB;  // 336
constexpr int kRowsPerBlk = 16;
constexpr int kBlkSteps = 16;
constexpr int kNBlks = kT / kBlkSteps;  // 128
constexpr int kGrid = 129;              // 128 scan blocks + 1 for row 2048
}
#define EXP_NEG_PEN 0.60653065971263342f
#define LN2 0.69314718055994530942

// Cross-block scratch (globals; L1 bypassed on read via __ldcg).
__device__ float  g_M[kNBlks * kB * kB];
__device__ float  g_chk[(kNBlks + 1) * kB];
__device__ int    g_Eb[kNBlks + 1];
__device__ double g_part[kNBlks];
__device__ float  g_es0_fin[kB];   // es0 row 2048 (written by block 128)

// Self-resetting global barriers (gen free-runs across graph replays).
struct Bar { unsigned cnt; unsigned gen; };
__device__ Bar g_bars[4];  // zero-initialized at module load

__device__ __forceinline__ void gbar(int id, unsigned nb) {
    __syncthreads();
    if (threadIdx.x == 0) {
        __threadfence();
        volatile unsigned* vgen = &g_bars[id].gen;
        unsigned g0 = *vgen;
        unsigned prev = atomicAdd(&g_bars[id].cnt, 1u);
        if (prev == nb - 1u) {
            g_bars[id].cnt = 0u;     // reset for next launch
            __threadfence();
            atomicAdd(&g_bars[id].gen, 1u);
        } else {
            while (*vgen == g0) {}
            __threadfence();
        }
    }
    __syncthreads();
}

// ---------------------------------------------------------------------------
// helpers
// ---------------------------------------------------------------------------
__device__ __forceinline__ void load16s(float d[16], const float* p) {
    const float4* p4 = (const float4*)p;
    float4 a = p4[0], b = p4[1], c = p4[2], e = p4[3];
    d[0]=a.x; d[1]=a.y; d[2]=a.z; d[3]=a.w;
    d[4]=b.x; d[5]=b.y; d[6]=b.z; d[7]=b.w;
    d[8]=c.x; d[9]=c.y; d[10]=c.z; d[11]=c.w;
    d[12]=e.x; d[13]=e.y; d[14]=e.z; d[15]=e.w;
}
__device__ __forceinline__ float4 ldcg4(const float* p) {
    return __ldcg((const float4*)p);
}
__device__ __forceinline__ float tree16(const float v[16]) {
    float a0=v[0]+v[1], a1=v[2]+v[3], a2=v[4]+v[5], a3=v[6]+v[7];
    float a4=v[8]+v[9], a5=v[10]+v[11], a6=v[12]+v[13], a7=v[14]+v[15];
    float b0=a0+a1, b1=a2+a3, b2=a4+a5, b3=a6+a7;
    return (b0+b1)+(b2+b3);
}
__device__ __forceinline__ float bfly16(float v) {
    v += __shfl_xor_sync(0xFFFFFFFFu, v, 1);
    v += __shfl_xor_sync(0xFFFFFFFFu, v, 2);
    v += __shfl_xor_sync(0xFFFFFFFFu, v, 4);
    v += __shfl_xor_sync(0xFFFFFFFFu, v, 8);
    return v;
}

__device__ __forceinline__ void compute_col(const float* __restrict__ base,
                                            int stride, int off,
                                            const float4* __restrict__ s4,
                                            float acc[kRowsPerBlk]) {
#pragma unroll
    for (int r = 0; r < kRowsPerBlk; r++) acc[r] = 0.0f;
    for (int k = 0; k < kS; k += 4) {
        float w0 = base[(k + 0) * stride + off];
        float w1 = base[(k + 1) * stride + off];
        float w2 = base[(k + 2) * stride + off];
        float w3 = base[(k + 3) * stride + off];
#pragma unroll
        for (int r = 0; r < kRowsPerBlk; r++) {
            float4 sv = s4[r * (kS / 4) + (k >> 2)];
            acc[r] = fmaf(sv.x, w0, fmaf(sv.y, w1, fmaf(sv.z, w2, fmaf(sv.w, w3, acc[r]))));
        }
    }
}

// ---------------------------------------------------------------------------
// THE kernel: prep -> compose (intra-block) -> [bar] -> serial (blk 0)
//             -> [bar] -> replay -> [bar] -> reduce (blk 0)
// ---------------------------------------------------------------------------
__global__ __launch_bounds__(256) void fused_kernel(
    const float* __restrict__ s_i,
    const float* __restrict__ Wa,
    const float* __restrict__ Wsp,
    const float* __restrict__ Wst,
    const void* __restrict__ actions_raw,
    float* __restrict__ out) {
    __shared__ __align__(16) float sm[kRowsPerBlk * kS];       // 32 KB
    __shared__ __align__(16) float s_es0[kBlkSteps * kB];
    __shared__ __align__(16) float s_es1[kBlkSteps * kB];
    __shared__ __align__(16) float s_est[kBlkSteps * kB];
    __shared__ __align__(16) float s_eac[kBlkSteps * kB];
    __shared__ double red[128];
    __shared__ int s_is64;

    const int tid  = threadIdx.x;
    const int blk  = blockIdx.x;
    const int row0 = blk * kRowsPerBlk;

    // ---- Phase 1: GEMM + softmaxes (identical math to R3's prep) ----
    if (tid == 0) {
        const unsigned* w = (const unsigned*)actions_raw;
        unsigned acc = 0;
#pragma unroll
        for (int j = 1; j < 64; j += 2) acc |= w[j];
        s_is64 = (acc == 0u) ? 1 : 0;
    }
    for (int idx = tid; idx < kRowsPerBlk * kS; idx += 256) {
        int r = idx >> 9;
        int k = idx & (kS - 1);
        int gr = row0 + r;
        sm[idx] = (gr <= kT) ? s_i[gr * kS + k] : 0.0f;
    }
    __syncthreads();

    float accA[kRowsPerBlk];
    float accB[kRowsPerBlk];
    const float4* s4 = (const float4*)sm;
    {
        int c = tid;
        const float* base; int stride, off;
        if (c < 288)      { base = Wa;  stride = 288; off = c; }
        else if (c < 320) { base = Wsp; stride = 32;  off = c - 288; }
        else              { base = Wst; stride = 16;  off = c - 320; }
        compute_col(base, stride, off, s4, accA);
    }
    const int c1 = tid + 256;
    if (c1 < kColsTot) {
        const float* base; int stride, off;
        if (c1 < 288)      { base = Wa;  stride = 288; off = c1; }
        else if (c1 < 320) { base = Wsp; stride = 32;  off = c1 - 288; }
        else               { base = Wst; stride = 16;  off = c1 - 320; }
        compute_col(base, stride, off, s4, accB);
    }
    __syncthreads();
#pragma unroll
    for (int r = 0; r < kRowsPerBlk; r++) sm[r * kS + tid] = accA[r];
    if (c1 < kColsTot) {
#pragma unroll
        for (int r = 0; r < kRowsPerBlk; r++) sm[r * kS + c1] = accB[r];
    }
    __syncthreads();

    {
        const int r = tid >> 4;
        const int b = tid & 15;
        const int i = row0 + r;
        const bool valid = (i <= kT);
        const int is64 = s_is64;

        if (valid) {
            if (i < kT) {
                int a;
                if (is64) a = (int)((const long long*)actions_raw)[i];
                else      a = ((const int*)actions_raw)[i];
                const float* L = &sm[r * kS + b * kA];
                float m = L[0];
#pragma unroll
                for (int j = 1; j < kA; j++) m = fmaxf(m, L[j]);
                float s = 0.0f;
#pragma unroll
                for (int j = 0; j < kA; j++) s += expf(L[j] - m);
                s_eac[r * kB + b] = expf(L[a] - m) / s;
            }
            float x0 = sm[r * kS + 288 + 2 * b];
            float x1 = sm[r * kS + 288 + 2 * b + 1];
            float m = fmaxf(x0, x1);
            float e0 = expf(x0 - m), e1 = expf(x1 - m);
            float inv = 1.0f / (e0 + e1);
            float es0 = e0 * inv;
            s_es0[r * kB + b] = es0;
            s_es1[r * kB + b] = e1 * inv;
            if (i == kT) g_es0_fin[b] = es0;   // block 128, r==0
        }
        {
            float x = sm[r * kS + 320 + b];
            float m = x;
            m = fmaxf(m, __shfl_xor_sync(0xFFFFFFFFu, m, 1));
            m = fmaxf(m, __shfl_xor_sync(0xFFFFFFFFu, m, 2));
            m = fmaxf(m, __shfl_xor_sync(0xFFFFFFFFu, m, 4));
            m = fmaxf(m, __shfl_xor_sync(0xFFFFFFFFu, m, 8));
            float e = expf(x - m);
            float s = e;
            s += __shfl_xor_sync(0xFFFFFFFFu, s, 1);
            s += __shfl_xor_sync(0xFFFFFFFFu, s, 2);
            s += __shfl_xor_sync(0xFFFFFFFFu, s, 4);
            s += __shfl_xor_sync(0xFFFFFFFFu, s, 8);
            if (valid) s_est[r * kB + b] = e / s;
        }
    }
    __syncthreads();

    // ---- Phase 2: compose (warp 0 of blocks 0..127, smem-fed) ----
    if (blk < kNBlks && tid < 32) {
        const int k = tid & 15;
        float P[16];
#pragma unroll
        for (int j = 0; j < 16; j++) P[j] = (j == k) ? 1.0f : 0.0f;
        for (int s = 0; s < kBlkSteps; s++) {
            if (blk == 0 && s == 0) continue;  // step 0 leaves buf unchanged
            float s0[16], s1[16], vv[16];
            load16s(s0, &s_es0[s * kB]);
            load16s(s1, &s_es1[s * kB]);
            load16s(vv, &s_est[s * kB]);
            float m[16];
#pragma unroll
            for (int j = 0; j < 16; j++) m[j] = s1[j] * P[j];
            float w = tree16(m);
#pragma unroll
            for (int j = 0; j < 16; j++)
                P[j] = fmaf(s0[j], P[j], (vv[j] * EXP_NEG_PEN) * w);
        }
        if (tid < 16) {
#pragma unroll
            for (int j = 0; j < 16; j++)
                g_M[blk * 256 + j * 16 + k] = P[j];
        }
    }

    gbar(0, kGrid);  // g_M + g_es0_fin ready

    // ---- Phase 3: serial scan over 128 matrices (block 0, warp 0) ----
    if (blk == 0 && tid < 32) {
        const int r = tid & 15;
        float Q[16];
        load16s(Q, &s_est[0]);  // block 0 owns row 0
        if (tid < 16) g_chk[tid] = Q[tid];
        if (tid == 0) g_Eb[0] = 0;
        int E = 0;

        float4 m0, m1, m2, m3;
        m0 = ldcg4(&g_M[r * 16 + 0]);
        m1 = ldcg4(&g_M[r * 16 + 4]);
        m2 = ldcg4(&g_M[r * 16 + 8]);
        m3 = ldcg4(&g_M[r * 16 + 12]);

        for (int j = 0; j < kNBlks; j++) {
            float4 n0, n1, n2, n3;
            if (j + 1 < kNBlks) {
                const float* Mn = &g_M[(j + 1) * 256 + r * 16];
                n0 = ldcg4(Mn + 0); n1 = ldcg4(Mn + 4);
                n2 = ldcg4(Mn + 8); n3 = ldcg4(Mn + 12);
            }
            float mm[16] = {m0.x, m0.y, m0.z, m0.w, m1.x, m1.y, m1.z, m1.w,
                            m2.x, m2.y, m2.z, m2.w, m3.x, m3.y, m3.z, m3.w};
            float pr[16];
#pragma unroll
            for (int kk = 0; kk < 16; kk++) pr[kk] = mm[kk] * Q[kk];
            float outr = tree16(pr);

            float Qn[16];
#pragma unroll
            for (int kk = 0; kk < 16; kk++)
                Qn[kk] = __shfl_sync(0xFFFFFFFFu, outr, kk);

            float ss = tree16(Qn);
            int e = ((__float_as_int(ss) >> 23) & 0xFF) - 127;
            float sc = __int_as_float((127 - e) << 23);
#pragma unroll
            for (int kk = 0; kk < 16; kk++) Q[kk] = Qn[kk] * sc;
            E += e;

            if (tid < 16) g_chk[(j + 1) * kB + tid] = Q[tid];
            if (tid == 0) g_Eb[j + 1] = E;
            m0 = n0; m1 = n1; m2 = n2; m3 = n3;
        }
    }

    gbar(1, kGrid);  // checkpoints ready

    // ---- Phase 4: replay (warp 0 of blocks 0..127, smem-fed) ----
    if (blk < kNBlks && tid < 32) {
        const int b = tid & 15;
        float Q = __ldcg(&g_chk[blk * kB + b]);
        const int E = __ldcg(&g_Eb[blk]);
        double acc = 0.0;

#pragma unroll
        for (int s = 0; s < kBlkSteps; s++) {
            int idx = s * kB + b;
            float s0 = s_es0[idx];
            float s1 = s_es1[idx];
            float v  = s_est[idx] * EXP_NEG_PEN;
            float ea = s_eac[idx];
            if (!(blk == 0 && s == 0)) {
                float t = bfly16(Q * s1);
                Q = fmaf(v, t, Q * s0);
            }
            float u = bfly16(Q * ea);
            acc += (double)logf(u);
        }
        acc += (double)(kBlkSteps * E) * LN2;

        if (blk == kNBlks - 1) {
            float u = bfly16(Q * __ldcg(&g_es0_fin[b]));
            acc += (double)logf(u) + (double)E * LN2;
        }
        if (tid == 0) g_part[blk] = acc;
    }

    gbar(2, kGrid);  // partials ready

    // ---- Phase 5: reduce (block 0) ----
    if (blk == 0) {
        if (tid < 128) red[tid] = __ldcg(&g_part[tid]);
        __syncthreads();
#pragma unroll
        for (int s = 64; s > 0; s >>= 1) {
            if (tid < s) red[tid] += red[tid + s];
            __syncthreads();
        }
        if (tid == 0) out[0] = (float)red[0];
    }
}

// ---------------------------------------------------------------------------
// Launch: one kernel. 129 blocks <= 148 SMs -> all co-resident, so the
// software global barriers cannot deadlock.
// ---------------------------------------------------------------------------
extern "C" void kernel_launch(void* const* d_in, const int* in_sizes, int n_in,
                              void* d_out, int out_size) {
    const float* s_i = (const float*)d_in[0];
    const float* Wa  = (const float*)d_in[1];
    const float* Wsp = (const float*)d_in[2];
    const float* Wst = (const float*)d_in[3];
    const void*  act = d_in[4];

    fused_kernel<<<kGrid, 256>>>(s_i, Wa, Wsp, Wst, act, (float*)d_out);
}

// round 5
// speedup vs baseline: 5.4765x; 1.1991x over previous
#include <cuda_runtime.h>

// ---------------------------------------------------------------------------
// Problem constants
// ---------------------------------------------------------------------------
namespace {
constexpr int kT = 2048;
constexpr int kS = 512;
constexpr int kB = 16;
constexpr int kA = 18;
constexpr int kColsTot = kB * kA + kB * 2 + kB;  // 336
constexpr int kRowsPerBlk = 16;
constexpr int kBlkSteps = 16;
constexpr int kNBlks = kT / kBlkSteps;  // 128
constexpr int kGrid = 129;
constexpr int kTStride = 20;            // padded row stride (words) for sm_t
}
#define EXP_NEG_PEN 0.60653065971263342f
#define LN2 0.69314718055994530942

// Cross-block scratch.
__device__ float  g_M[kNBlks * kB * kB];
__device__ float  g_chk[(kNBlks + 1) * kB];
__device__ int    g_Eb[kNBlks + 1];
__device__ double g_part[kNBlks];
__device__ float  g_es0_fin[kB];

// Self-resetting global barriers.
struct Bar { unsigned cnt; unsigned gen; };
__device__ Bar g_bars[4];

__device__ __forceinline__ void gbar(int id, unsigned nb) {
    __syncthreads();
    if (threadIdx.x == 0) {
        __threadfence();
        volatile unsigned* vgen = &g_bars[id].gen;
        unsigned g0 = *vgen;
        unsigned prev = atomicAdd(&g_bars[id].cnt, 1u);
        if (prev == nb - 1u) {
            g_bars[id].cnt = 0u;
            __threadfence();
            atomicAdd(&g_bars[id].gen, 1u);
        } else {
            while (*vgen == g0) {}
            __threadfence();
        }
    }
    __syncthreads();
}

// ---------------------------------------------------------------------------
// packed f32x2 helpers
// ---------------------------------------------------------------------------
__device__ __forceinline__ void ffma2(unsigned long long& d,
                                      unsigned long long a,
                                      unsigned long long b) {
    asm("fma.rn.f32x2 %0, %1, %2, %0;" : "+l"(d) : "l"(a), "l"(b));
}
__device__ __forceinline__ unsigned long long bcast2(float w) {
    unsigned long long r;
    asm("mov.b64 %0, {%1, %1};" : "=l"(r) : "f"(w));
    return r;
}
__device__ __forceinline__ float lo32(unsigned long long v) {
    return __uint_as_float((unsigned)(v & 0xffffffffull));
}
__device__ __forceinline__ float hi32(unsigned long long v) {
    return __uint_as_float((unsigned)(v >> 32));
}

__device__ __forceinline__ void load16s(float d[16], const float* p) {
    const float4* p4 = (const float4*)p;
    float4 a = p4[0], b = p4[1], c = p4[2], e = p4[3];
    d[0]=a.x; d[1]=a.y; d[2]=a.z; d[3]=a.w;
    d[4]=b.x; d[5]=b.y; d[6]=b.z; d[7]=b.w;
    d[8]=c.x; d[9]=c.y; d[10]=c.z; d[11]=c.w;
    d[12]=e.x; d[13]=e.y; d[14]=e.z; d[15]=e.w;
}
__device__ __forceinline__ float4 ldcg4(const float* p) {
    return __ldcg((const float4*)p);
}
__device__ __forceinline__ float tree16(const float v[16]) {
    float a0=v[0]+v[1], a1=v[2]+v[3], a2=v[4]+v[5], a3=v[6]+v[7];
    float a4=v[8]+v[9], a5=v[10]+v[11], a6=v[12]+v[13], a7=v[14]+v[15];
    float b0=a0+a1, b1=a2+a3, b2=a4+a5, b3=a6+a7;
    return (b0+b1)+(b2+b3);
}
__device__ __forceinline__ float bfly16(float v) {
    v += __shfl_xor_sync(0xFFFFFFFFu, v, 1);
    v += __shfl_xor_sync(0xFFFFFFFFu, v, 2);
    v += __shfl_xor_sync(0xFFFFFFFFu, v, 4);
    v += __shfl_xor_sync(0xFFFFFFFFu, v, 8);
    return v;
}

// ---------------------------------------------------------------------------
// GEMM column: 16 rows x K=512 for one output column, f32x2 packed,
// W software-prefetched (distance = 8 k's). sm_t layout: [k*20 + r].
// ---------------------------------------------------------------------------
__device__ __forceinline__ void compute_col2(const float* __restrict__ base,
                                             int stride, int off,
                                             const float* __restrict__ sm_t,
                                             unsigned long long acc2[8]) {
#pragma unroll
    for (int p = 0; p < 8; p++) acc2[p] = 0ull;

    float wb[8];
#pragma unroll
    for (int j = 0; j < 8; j++) wb[j] = base[j * stride + off];

    for (int k8 = 0; k8 < kS / 8; k8++) {
        float wn[8];
        const bool more = (k8 + 1 < kS / 8);
#pragma unroll
        for (int j = 0; j < 8; j++)
            if (more) wn[j] = base[((k8 + 1) * 8 + j) * stride + off];
#pragma unroll
        for (int j = 0; j < 8; j++) {
            const int k = k8 * 8 + j;
            unsigned long long w2 = bcast2(wb[j]);
            const ulonglong2* p = (const ulonglong2*)(sm_t + k * kTStride);
            ulonglong2 q0 = p[0];  // rows 0..3
            ulonglong2 q1 = p[1];  // rows 4..7
            ulonglong2 q2 = p[2];  // rows 8..11
            ulonglong2 q3 = p[3];  // rows 12..15
            ffma2(acc2[0], q0.x, w2); ffma2(acc2[1], q0.y, w2);
            ffma2(acc2[2], q1.x, w2); ffma2(acc2[3], q1.y, w2);
            ffma2(acc2[4], q2.x, w2); ffma2(acc2[5], q2.y, w2);
            ffma2(acc2[6], q3.x, w2); ffma2(acc2[7], q3.y, w2);
        }
#pragma unroll
        for (int j = 0; j < 8; j++) wb[j] = wn[j];
    }
}

// ---------------------------------------------------------------------------
// THE kernel
// ---------------------------------------------------------------------------
__global__ __launch_bounds__(256) void fused_kernel(
    const float* __restrict__ s_i,
    const float* __restrict__ Wa,
    const float* __restrict__ Wsp,
    const float* __restrict__ Wst,
    const void* __restrict__ actions_raw,
    float* __restrict__ out) {
    __shared__ __align__(16) float sm_t[kS * kTStride];        // 40 KB
    __shared__ __align__(16) float s_es0[kBlkSteps * kB];
    __shared__ __align__(16) float s_es1[kBlkSteps * kB];
    __shared__ __align__(16) float s_est[kBlkSteps * kB];
    __shared__ __align__(16) float s_eac[kBlkSteps * kB];
    __shared__ double red[128];
    __shared__ int s_is64;

    const int tid  = threadIdx.x;
    const int blk  = blockIdx.x;
    const int row0 = blk * kRowsPerBlk;

    // ---- Phase 1a: stage s_i transposed: sm_t[k*20 + r] ----
    if (tid == 0) {
        const unsigned* w = (const unsigned*)actions_raw;
        unsigned acc = 0;
#pragma unroll
        for (int j = 1; j < 64; j += 2) acc |= w[j];
        s_is64 = (acc == 0u) ? 1 : 0;
    }
    for (int idx = tid; idx < kRowsPerBlk * kS; idx += 256) {
        int r = idx >> 9;
        int k = idx & (kS - 1);
        int gr = row0 + r;
        sm_t[k * kTStride + r] = (gr <= kT) ? s_i[gr * kS + k] : 0.0f;
    }
    __syncthreads();

    // ---- Phase 1b: GEMM (f32x2 packed, prefetched) ----
    unsigned long long accA[8];
    unsigned long long accB[8];
    {
        int c = tid;
        const float* base; int stride, off;
        if (c < 288)      { base = Wa;  stride = 288; off = c; }
        else if (c < 320) { base = Wsp; stride = 32;  off = c - 288; }
        else              { base = Wst; stride = 16;  off = c - 320; }
        compute_col2(base, stride, off, sm_t, accA);
    }
    const int c1 = tid + 256;
    if (c1 < kColsTot) {
        const float* base; int stride, off;
        if (c1 < 288)      { base = Wa;  stride = 288; off = c1; }
        else if (c1 < 320) { base = Wsp; stride = 32;  off = c1 - 288; }
        else               { base = Wst; stride = 16;  off = c1 - 320; }
        compute_col2(base, stride, off, sm_t, accB);
    }
    __syncthreads();  // all sm_t reads done; reuse as logits [r*336 + c]

    float* smL = sm_t;
#pragma unroll
    for (int p = 0; p < 8; p++) {
        smL[(2 * p    ) * kColsTot + tid] = lo32(accA[p]);
        smL[(2 * p + 1) * kColsTot + tid] = hi32(accA[p]);
    }
    if (c1 < kColsTot) {
#pragma unroll
        for (int p = 0; p < 8; p++) {
            smL[(2 * p    ) * kColsTot + c1] = lo32(accB[p]);
            smL[(2 * p + 1) * kColsTot + c1] = hi32(accB[p]);
        }
    }
    __syncthreads();

    // ---- Phase 1c: softmaxes ----
    {
        const int r = tid >> 4;
        const int b = tid & 15;
        const int i = row0 + r;
        const bool valid = (i <= kT);
        const int is64 = s_is64;

        if (valid) {
            if (i < kT) {
                int a;
                if (is64) a = (int)((const long long*)actions_raw)[i];
                else      a = ((const int*)actions_raw)[i];
                const float* L = &smL[r * kColsTot + b * kA];
                float m = L[0];
#pragma unroll
                for (int j = 1; j < kA; j++) m = fmaxf(m, L[j]);
                float s = 0.0f;
#pragma unroll
                for (int j = 0; j < kA; j++) s += expf(L[j] - m);
                s_eac[r * kB + b] = expf(L[a] - m) / s;
            }
            float x0 = smL[r * kColsTot + 288 + 2 * b];
            float x1 = smL[r * kColsTot + 288 + 2 * b + 1];
            float m = fmaxf(x0, x1);
            float e0 = expf(x0 - m), e1 = expf(x1 - m);
            float inv = 1.0f / (e0 + e1);
            float es0 = e0 * inv;
            s_es0[r * kB + b] = es0;
            s_es1[r * kB + b] = e1 * inv;
            if (i == kT) g_es0_fin[b] = es0;
        }
        {
            float x = smL[r * kColsTot + 320 + b];
            float m = x;
            m = fmaxf(m, __shfl_xor_sync(0xFFFFFFFFu, m, 1));
            m = fmaxf(m, __shfl_xor_sync(0xFFFFFFFFu, m, 2));
            m = fmaxf(m, __shfl_xor_sync(0xFFFFFFFFu, m, 4));
            m = fmaxf(m, __shfl_xor_sync(0xFFFFFFFFu, m, 8));
            float e = expf(x - m);
            float s = e;
            s += __shfl_xor_sync(0xFFFFFFFFu, s, 1);
            s += __shfl_xor_sync(0xFFFFFFFFu, s, 2);
            s += __shfl_xor_sync(0xFFFFFFFFu, s, 4);
            s += __shfl_xor_sync(0xFFFFFFFFu, s, 8);
            if (valid) s_est[r * kB + b] = e / s;
        }
    }
    __syncthreads();

    // ---- Phase 2: compose ----
    if (blk < kNBlks && tid < 32) {
        const int k = tid & 15;
        float P[16];
#pragma unroll
        for (int j = 0; j < 16; j++) P[j] = (j == k) ? 1.0f : 0.0f;
        for (int s = 0; s < kBlkSteps; s++) {
            if (blk == 0 && s == 0) continue;
            float s0[16], s1[16], vv[16];
            load16s(s0, &s_es0[s * kB]);
            load16s(s1, &s_es1[s * kB]);
            load16s(vv, &s_est[s * kB]);
            float m[16];
#pragma unroll
            for (int j = 0; j < 16; j++) m[j] = s1[j] * P[j];
            float w = tree16(m);
#pragma unroll
            for (int j = 0; j < 16; j++)
                P[j] = fmaf(s0[j], P[j], (vv[j] * EXP_NEG_PEN) * w);
        }
        if (tid < 16) {
#pragma unroll
            for (int j = 0; j < 16; j++)
                g_M[blk * 256 + j * 16 + k] = P[j];
        }
    }

    gbar(0, kGrid);

    // ---- Phase 3: serial scan (block 0, warp 0) ----
    if (blk == 0 && tid < 32) {
        const int r = tid & 15;
        float Q[16];
        load16s(Q, &s_est[0]);
        if (tid < 16) g_chk[tid] = Q[tid];
        if (tid == 0) g_Eb[0] = 0;
        int E = 0;

        float4 m0 = ldcg4(&g_M[r * 16 + 0]);
        float4 m1 = ldcg4(&g_M[r * 16 + 4]);
        float4 m2 = ldcg4(&g_M[r * 16 + 8]);
        float4 m3 = ldcg4(&g_M[r * 16 + 12]);

        for (int j = 0; j < kNBlks; j++) {
            float4 n0, n1, n2, n3;
            if (j + 1 < kNBlks) {
                const float* Mn = &g_M[(j + 1) * 256 + r * 16];
                n0 = ldcg4(Mn + 0); n1 = ldcg4(Mn + 4);
                n2 = ldcg4(Mn + 8); n3 = ldcg4(Mn + 12);
            }
            float mm[16] = {m0.x, m0.y, m0.z, m0.w, m1.x, m1.y, m1.z, m1.w,
                            m2.x, m2.y, m2.z, m2.w, m3.x, m3.y, m3.z, m3.w};
            float pr[16];
#pragma unroll
            for (int kk = 0; kk < 16; kk++) pr[kk] = mm[kk] * Q[kk];
            float outr = tree16(pr);

            float Qn[16];
#pragma unroll
            for (int kk = 0; kk < 16; kk++)
                Qn[kk] = __shfl_sync(0xFFFFFFFFu, outr, kk);

            float ss = tree16(Qn);
            int e = ((__float_as_int(ss) >> 23) & 0xFF) - 127;
            float sc = __int_as_float((127 - e) << 23);
#pragma unroll
            for (int kk = 0; kk < 16; kk++) Q[kk] = Qn[kk] * sc;
            E += e;

            if (tid < 16) g_chk[(j + 1) * kB + tid] = Q[tid];
            if (tid == 0) g_Eb[j + 1] = E;
            m0 = n0; m1 = n1; m2 = n2; m3 = n3;
        }
    }

    gbar(1, kGrid);

    // ---- Phase 4: replay ----
    if (blk < kNBlks && tid < 32) {
        const int b = tid & 15;
        float Q = __ldcg(&g_chk[blk * kB + b]);
        const int E = __ldcg(&g_Eb[blk]);
        double acc = 0.0;

#pragma unroll
        for (int s = 0; s < kBlkSteps; s++) {
            int idx = s * kB + b;
            float s0 = s_es0[idx];
            float s1 = s_es1[idx];
            float v  = s_est[idx] * EXP_NEG_PEN;
            float ea = s_eac[idx];
            if (!(blk == 0 && s == 0)) {
                float t = bfly16(Q * s1);
                Q = fmaf(v, t, Q * s0);
            }
            float u = bfly16(Q * ea);
            acc += (double)logf(u);
        }
        acc += (double)(kBlkSteps * E) * LN2;

        if (blk == kNBlks - 1) {
            float u = bfly16(Q * __ldcg(&g_es0_fin[b]));
            acc += (double)logf(u) + (double)E * LN2;
        }
        if (tid == 0) g_part[blk] = acc;
    }

    gbar(2, kGrid);

    // ---- Phase 5: reduce (block 0) ----
    if (blk == 0) {
        if (tid < 128) red[tid] = __ldcg(&g_part[tid]);
        __syncthreads();
#pragma unroll
        for (int s = 64; s > 0; s >>= 1) {
            if (tid < s) red[tid] += red[tid + s];
            __syncthreads();
        }
        if (tid == 0) out[0] = (float)red[0];
    }
}

extern "C" void kernel_launch(void* const* d_in, const int* in_sizes, int n_in,
                              void* d_out, int out_size) {
    const float* s_i = (const float*)d_in[0];
    const float* Wa  = (const float*)d_in[1];
    const float* Wsp = (const float*)d_in[2];
    const float* Wst = (const float*)d_in[3];
    const void*  act = d_in[4];

    fused_kernel<<<kGrid, 256>>>(s_i, Wa, Wsp, Wst, act, (float*)d_out);
}

// round 6
// speedup vs baseline: 5.7709x; 1.0538x over previous
#include <cuda_runtime.h>

// ---------------------------------------------------------------------------
// Problem constants
// ---------------------------------------------------------------------------
namespace {
constexpr int kT = 2048;
constexpr int kS = 512;
constexpr int kB = 16;
constexpr int kA = 18;
constexpr int kColsTot = 336;           // 288 + 32 + 16
constexpr int kRowsPerBlk = 16;
constexpr int kBlkSteps = 16;
constexpr int kNBlks = kT / kBlkSteps;  // 128
constexpr int kGrid = 129;
constexpr int kThreads = 672;           // 2 x 336 (col, row-half)
constexpr int kTStride = 20;            // padded row stride (words) for smT
constexpr int kTileRows = 16;
constexpr int kNTiles = kS / kTileRows; // 32
constexpr int kWTile = kTileRows * kColsTot;  // 5376 floats
// dynamic smem layout (float offsets)
constexpr int kOffT   = 0;                    // smT: 512*20 = 10240
constexpr int kOffW   = 10240;                // W double buffer: 2*5376
constexpr int kOffE0  = kOffW + 2 * kWTile;   // 20992
constexpr int kOffE1  = kOffE0 + 256;
constexpr int kOffEs  = kOffE1 + 256;
constexpr int kOffEa  = kOffEs + 256;
constexpr int kOffRed = kOffEa + 256;         // 22016 (byte 88064, 8-aligned)
constexpr int kSmemFloats = kOffRed + 256;    // red = 128 doubles
constexpr int kSmemBytes = kSmemFloats * 4;   // 89088
}
#define EXP_NEG_PEN 0.60653065971263342f
#define LN2 0.69314718055994530942

// Cross-block scratch.
__device__ float  g_M[kNBlks * kB * kB];
__device__ float  g_chk[(kNBlks + 1) * kB];
__device__ int    g_Eb[kNBlks + 1];
__device__ double g_part[kNBlks];
__device__ float  g_es0_fin[kB];

// Self-resetting global barriers.
struct Bar { unsigned cnt; unsigned gen; };
__device__ Bar g_bars[4];

__device__ __forceinline__ void gbar(int id, unsigned nb) {
    __syncthreads();
    if (threadIdx.x == 0) {
        __threadfence();
        volatile unsigned* vgen = &g_bars[id].gen;
        unsigned g0 = *vgen;
        unsigned prev = atomicAdd(&g_bars[id].cnt, 1u);
        if (prev == nb - 1u) {
            g_bars[id].cnt = 0u;
            __threadfence();
            atomicAdd(&g_bars[id].gen, 1u);
        } else {
            while (*vgen == g0) { __nanosleep(64); }
            __threadfence();
        }
    }
    __syncthreads();
}

// ---------------------------------------------------------------------------
// helpers
// ---------------------------------------------------------------------------
__device__ __forceinline__ void ffma2(unsigned long long& d,
                                      unsigned long long a,
                                      unsigned long long b) {
    asm("fma.rn.f32x2 %0, %1, %2, %0;" : "+l"(d) : "l"(a), "l"(b));
}
__device__ __forceinline__ unsigned long long bcast2(float w) {
    unsigned long long r;
    asm("mov.b64 %0, {%1, %1};" : "=l"(r) : "f"(w));
    return r;
}
__device__ __forceinline__ float lo32(unsigned long long v) {
    return __uint_as_float((unsigned)(v & 0xffffffffull));
}
__device__ __forceinline__ float hi32(unsigned long long v) {
    return __uint_as_float((unsigned)(v >> 32));
}
__device__ __forceinline__ void cp_async16(float* sdst, const float* gsrc) {
    unsigned a = (unsigned)__cvta_generic_to_shared(sdst);
    asm volatile("cp.async.cg.shared.global [%0], [%1], 16;" :: "r"(a), "l"(gsrc));
}
#define CP_COMMIT() asm volatile("cp.async.commit_group;")
#define CP_WAIT1()  asm volatile("cp.async.wait_group 1;")

__device__ __forceinline__ void load16s(float d[16], const float* p) {
    const float4* p4 = (const float4*)p;
    float4 a = p4[0], b = p4[1], c = p4[2], e = p4[3];
    d[0]=a.x; d[1]=a.y; d[2]=a.z; d[3]=a.w;
    d[4]=b.x; d[5]=b.y; d[6]=b.z; d[7]=b.w;
    d[8]=c.x; d[9]=c.y; d[10]=c.z; d[11]=c.w;
    d[12]=e.x; d[13]=e.y; d[14]=e.z; d[15]=e.w;
}
__device__ __forceinline__ float4 ldcg4(const float* p) {
    return __ldcg((const float4*)p);
}
__device__ __forceinline__ float tree16(const float v[16]) {
    float a0=v[0]+v[1], a1=v[2]+v[3], a2=v[4]+v[5], a3=v[6]+v[7];
    float a4=v[8]+v[9], a5=v[10]+v[11], a6=v[12]+v[13], a7=v[14]+v[15];
    float b0=a0+a1, b1=a2+a3, b2=a4+a5, b3=a6+a7;
    return (b0+b1)+(b2+b3);
}
__device__ __forceinline__ float bfly16(float v) {
    v += __shfl_xor_sync(0xFFFFFFFFu, v, 1);
    v += __shfl_xor_sync(0xFFFFFFFFu, v, 2);
    v += __shfl_xor_sync(0xFFFFFFFFu, v, 4);
    v += __shfl_xor_sync(0xFFFFFFFFu, v, 8);
    return v;
}

// Stage one 16x336 W tile (rows k0..k0+15 of the concatenated W) into smem.
// 1344 float4 = exactly 2 per thread, fully coalesced.
__device__ __forceinline__ void stage_tile(float* dst,
                                           const float* __restrict__ Wa,
                                           const float* __restrict__ Wsp,
                                           const float* __restrict__ Wst,
                                           int k0, int tid) {
#pragma unroll
    for (int h = 0; h < 2; h++) {
        int q = tid + h * kThreads;      // 0..1343
        int j = q / 84;                  // row within tile
        int col = (q % 84) * 4;          // 4-aligned column
        int k = k0 + j;
        const float* src;
        if (col < 288)      src = Wa  + k * 288 + col;
        else if (col < 320) src = Wsp + k * 32 + (col - 288);
        else                src = Wst + k * 16 + (col - 320);
        cp_async16(dst + j * kColsTot + col, src);
    }
}

// ---------------------------------------------------------------------------
// THE kernel
// ---------------------------------------------------------------------------
__global__ __launch_bounds__(kThreads) void fused_kernel(
    const float* __restrict__ s_i,
    const float* __restrict__ Wa,
    const float* __restrict__ Wsp,
    const float* __restrict__ Wst,
    const void* __restrict__ actions_raw,
    float* __restrict__ out) {
    extern __shared__ __align__(16) float smem[];
    float* smT  = smem + kOffT;     // staged s_i transposed [k*20 + r]
    float* smW  = smem + kOffW;     // W tile double buffer
    float* sE0  = smem + kOffE0;
    float* sE1  = smem + kOffE1;
    float* sEs  = smem + kOffEs;
    float* sEa  = smem + kOffEa;
    double* red = (double*)(smem + kOffRed);
    __shared__ int s_is64;

    const int tid  = threadIdx.x;
    const int blk  = blockIdx.x;
    const int row0 = blk * kRowsPerBlk;

    // ---- Phase 1a: stage s_i transposed ----
    if (tid == 0) {
        const unsigned* w = (const unsigned*)actions_raw;
        unsigned acc = 0;
#pragma unroll
        for (int j = 1; j < 64; j += 2) acc |= w[j];
        s_is64 = (acc == 0u) ? 1 : 0;
    }
    for (int idx = tid; idx < kRowsPerBlk * kS; idx += kThreads) {
        int r = idx >> 9;
        int k = idx & (kS - 1);
        int gr = row0 + r;
        smT[k * kTStride + r] = (gr <= kT) ? s_i[gr * kS + k] : 0.0f;
    }

    // ---- Phase 1b: GEMM, cp.async double-buffered W tiles ----
    const int c    = tid % kColsTot;
    const int half = tid / kColsTot;     // 0 or 1
    const int r0   = half * 8;
    const int p0   = blk & (kNTiles - 1);  // per-block rotation

    stage_tile(smW,          Wa, Wsp, Wst, ((p0 + 0) & 31) * kTileRows, tid);
    CP_COMMIT();
    stage_tile(smW + kWTile, Wa, Wsp, Wst, ((p0 + 1) & 31) * kTileRows, tid);
    CP_COMMIT();

    unsigned long long acc2[4] = {0ull, 0ull, 0ull, 0ull};

    for (int i = 0; i < kNTiles; i++) {
        CP_WAIT1();
        __syncthreads();   // tile i visible to all; also covers phase-1a staging on i==0
        const int phys = (p0 + i) & 31;
        const float* wrow = smW + (i & 1) * kWTile;
#pragma unroll
        for (int j = 0; j < kTileRows; j++) {
            const int k = phys * kTileRows + j;
            unsigned long long w2 = bcast2(wrow[j * kColsTot + c]);
            const ulonglong2* sp = (const ulonglong2*)(smT + k * kTStride + r0);
            ulonglong2 q0 = sp[0];
            ulonglong2 q1 = sp[1];
            ffma2(acc2[0], q0.x, w2);
            ffma2(acc2[1], q0.y, w2);
            ffma2(acc2[2], q1.x, w2);
            ffma2(acc2[3], q1.y, w2);
        }
        __syncthreads();   // all reads of buffer (i&1) done
        if (i + 2 < kNTiles) {
            stage_tile(smW + (i & 1) * kWTile, Wa, Wsp, Wst,
                       ((p0 + i + 2) & 31) * kTileRows, tid);
            CP_COMMIT();
        }
    }

    // ---- Phase 1c: write logits into smT region (smL[r*336 + c]) ----
    float* smL = smT;
#pragma unroll
    for (int p = 0; p < 4; p++) {
        smL[(r0 + 2 * p    ) * kColsTot + c] = lo32(acc2[p]);
        smL[(r0 + 2 * p + 1) * kColsTot + c] = hi32(acc2[p]);
    }
    __syncthreads();

    // ---- Phase 1d: softmaxes (threads 0..255: r = tid>>4, b = tid&15) ----
    if (tid < 256) {
        const int r = tid >> 4;
        const int b = tid & 15;
        const int i = row0 + r;
        const bool valid = (i <= kT);
        const int is64 = s_is64;

        if (valid) {
            if (i < kT) {
                int a;
                if (is64) a = (int)((const long long*)actions_raw)[i];
                else      a = ((const int*)actions_raw)[i];
                const float* L = &smL[r * kColsTot + b * kA];
                float m = L[0];
#pragma unroll
                for (int j = 1; j < kA; j++) m = fmaxf(m, L[j]);
                float s = 0.0f;
#pragma unroll
                for (int j = 0; j < kA; j++) s += expf(L[j] - m);
                sEa[r * kB + b] = expf(L[a] - m) / s;
            }
            float x0 = smL[r * kColsTot + 288 + 2 * b];
            float x1 = smL[r * kColsTot + 288 + 2 * b + 1];
            float m = fmaxf(x0, x1);
            float e0 = expf(x0 - m), e1 = expf(x1 - m);
            float inv = 1.0f / (e0 + e1);
            float es0 = e0 * inv;
            sE0[r * kB + b] = es0;
            sE1[r * kB + b] = e1 * inv;
            if (i == kT) g_es0_fin[b] = es0;
        }
        {
            float x = smL[r * kColsTot + 320 + b];
            float m = x;
            m = fmaxf(m, __shfl_xor_sync(0xFFFFFFFFu, m, 1));
            m = fmaxf(m, __shfl_xor_sync(0xFFFFFFFFu, m, 2));
            m = fmaxf(m, __shfl_xor_sync(0xFFFFFFFFu, m, 4));
            m = fmaxf(m, __shfl_xor_sync(0xFFFFFFFFu, m, 8));
            float e = expf(x - m);
            float s = e;
            s += __shfl_xor_sync(0xFFFFFFFFu, s, 1);
            s += __shfl_xor_sync(0xFFFFFFFFu, s, 2);
            s += __shfl_xor_sync(0xFFFFFFFFu, s, 4);
            s += __shfl_xor_sync(0xFFFFFFFFu, s, 8);
            if (valid) sEs[r * kB + b] = e / s;
        }
    }
    __syncthreads();

    // ---- Phase 2: compose (warp 0 of blocks 0..127) ----
    if (blk < kNBlks && tid < 32) {
        const int k = tid & 15;
        float P[16];
#pragma unroll
        for (int j = 0; j < 16; j++) P[j] = (j == k) ? 1.0f : 0.0f;
        for (int s = 0; s < kBlkSteps; s++) {
            if (blk == 0 && s == 0) continue;
            float s0[16], s1[16], vv[16];
            load16s(s0, &sE0[s * kB]);
            load16s(s1, &sE1[s * kB]);
            load16s(vv, &sEs[s * kB]);
            float m[16];
#pragma unroll
            for (int j = 0; j < 16; j++) m[j] = s1[j] * P[j];
            float w = tree16(m);
#pragma unroll
            for (int j = 0; j < 16; j++)
                P[j] = fmaf(s0[j], P[j], (vv[j] * EXP_NEG_PEN) * w);
        }
        if (tid < 16) {
#pragma unroll
            for (int j = 0; j < 16; j++)
                g_M[blk * 256 + j * 16 + k] = P[j];
        }
    }

    gbar(0, kGrid);

    // ---- Phase 3: serial scan (block 0, warp 0), prefetch distance 2 ----
    if (blk == 0 && tid < 32) {
        const int r = tid & 15;
        float Q[16];
        load16s(Q, &sEs[0]);
        if (tid < 16) g_chk[tid] = Q[tid];
        if (tid == 0) g_Eb[0] = 0;
        int E = 0;

        float4 a0 = ldcg4(&g_M[0 * 256 + r * 16 + 0]);
        float4 a1 = ldcg4(&g_M[0 * 256 + r * 16 + 4]);
        float4 a2 = ldcg4(&g_M[0 * 256 + r * 16 + 8]);
        float4 a3 = ldcg4(&g_M[0 * 256 + r * 16 + 12]);
        float4 b0 = ldcg4(&g_M[1 * 256 + r * 16 + 0]);
        float4 b1 = ldcg4(&g_M[1 * 256 + r * 16 + 4]);
        float4 b2 = ldcg4(&g_M[1 * 256 + r * 16 + 8]);
        float4 b3 = ldcg4(&g_M[1 * 256 + r * 16 + 12]);

        for (int j = 0; j < kNBlks; j++) {
            float4 c0, c1, c2, c3;
            if (j + 2 < kNBlks) {
                const float* Mn = &g_M[(j + 2) * 256 + r * 16];
                c0 = ldcg4(Mn + 0); c1 = ldcg4(Mn + 4);
                c2 = ldcg4(Mn + 8); c3 = ldcg4(Mn + 12);
            }
            float mm[16] = {a0.x, a0.y, a0.z, a0.w, a1.x, a1.y, a1.z, a1.w,
                            a2.x, a2.y, a2.z, a2.w, a3.x, a3.y, a3.z, a3.w};
            float pr[16];
#pragma unroll
            for (int kk = 0; kk < 16; kk++) pr[kk] = mm[kk] * Q[kk];
            float outr = tree16(pr);

            float Qn[16];
#pragma unroll
            for (int kk = 0; kk < 16; kk++)
                Qn[kk] = __shfl_sync(0xFFFFFFFFu, outr, kk);

            float ss = tree16(Qn);
            int e = ((__float_as_int(ss) >> 23) & 0xFF) - 127;
            float sc = __int_as_float((127 - e) << 23);
#pragma unroll
            for (int kk = 0; kk < 16; kk++) Q[kk] = Qn[kk] * sc;
            E += e;

            if (tid < 16) g_chk[(j + 1) * kB + tid] = Q[tid];
            if (tid == 0) g_Eb[j + 1] = E;
            a0 = b0; a1 = b1; a2 = b2; a3 = b3;
            b0 = c0; b1 = c1; b2 = c2; b3 = c3;
        }
    }

    gbar(1, kGrid);

    // ---- Phase 4: replay ----
    if (blk < kNBlks && tid < 32) {
        const int b = tid & 15;
        float Q = __ldcg(&g_chk[blk * kB + b]);
        const int E = __ldcg(&g_Eb[blk]);
        double acc = 0.0;

#pragma unroll
        for (int s = 0; s < kBlkSteps; s++) {
            int idx = s * kB + b;
            float s0 = sE0[idx];
            float s1 = sE1[idx];
            float v  = sEs[idx] * EXP_NEG_PEN;
            float ea = sEa[idx];
            if (!(blk == 0 && s == 0)) {
                float t = bfly16(Q * s1);
                Q = fmaf(v, t, Q * s0);
            }
            float u = bfly16(Q * ea);
            acc += (double)logf(u);
        }
        acc += (double)(kBlkSteps * E) * LN2;

        if (blk == kNBlks - 1) {
            float u = bfly16(Q * __ldcg(&g_es0_fin[b]));
            acc += (double)logf(u) + (double)E * LN2;
        }
        if (tid == 0) g_part[blk] = acc;
    }

    gbar(2, kGrid);

    // ---- Phase 5: reduce (block 0) ----
    if (blk == 0) {
        if (tid < 128) red[tid] = __ldcg(&g_part[tid]);
        __syncthreads();
#pragma unroll
        for (int s = 64; s > 0; s >>= 1) {
            if (tid < s) red[tid] += red[tid + s];
            __syncthreads();
        }
        if (tid == 0) out[0] = (float)red[0];
    }
}

extern "C" void kernel_launch(void* const* d_in, const int* in_sizes, int n_in,
                              void* d_out, int out_size) {
    const float* s_i = (const float*)d_in[0];
    const float* Wa  = (const float*)d_in[1];
    const float* Wsp = (const float*)d_in[2];
    const float* Wst = (const float*)d_in[3];
    const void*  act = d_in[4];

    cudaFuncSetAttribute(fused_kernel,
                         cudaFuncAttributeMaxDynamicSharedMemorySize,
                         kSmemBytes);
    fused_kernel<<<kGrid, kThreads, kSmemBytes>>>(s_i, Wa, Wsp, Wst, act,
                                                  (float*)d_out);
}

// round 7
// speedup vs baseline: 6.5796x; 1.1401x over previous
#include <cuda_runtime.h>

// ---------------------------------------------------------------------------
// Problem constants
// ---------------------------------------------------------------------------
namespace {
constexpr int kT = 2048;
constexpr int kS = 512;
constexpr int kB = 16;
constexpr int kA = 18;
constexpr int kColsTot = 336;           // 288 + 32 + 16
constexpr int kRowsPerBlk = 16;
constexpr int kBlkSteps = 16;
constexpr int kNBlks = kT / kBlkSteps;  // 128
constexpr int kGrid = 129;
constexpr int kThreads = 672;           // 2 khalf x 2 rowhalf x 168 colpairs
constexpr int kTStride = 20;            // padded row stride (words) for smT
constexpr int kTileRows = 16;
constexpr int kNT = 16;                 // double-tile iterations (16 rows/half)
constexpr int kKHalf = 256;
constexpr int kDT = 2 * kTileRows * kColsTot;  // 10752 floats per double-tile
// dynamic smem layout (float offsets)
constexpr int kOffT   = 0;                      // smT: 512*20 = 10240
constexpr int kOffW   = 10240;                  // W double-tile x2 = 21504
constexpr int kOffE0  = kOffW + 2 * kDT;        // 31744
constexpr int kOffE1  = kOffE0 + 256;
constexpr int kOffEs  = kOffE1 + 256;
constexpr int kOffEa  = kOffEs + 256;
constexpr int kOffRed = kOffEa + 256;           // byte 131072, 8-aligned
constexpr int kSmemFloats = kOffRed + 256;
constexpr int kSmemBytes = kSmemFloats * 4;     // 132096
}
#define EXP_NEG_PEN 0.60653065971263342f
#define LN2 0.69314718055994530942

// Cross-block scratch.
__device__ float  g_M[kNBlks * kB * kB];
__device__ float  g_chk[(kNBlks + 1) * kB];
__device__ int    g_Eb[kNBlks + 1];
__device__ double g_part[kNBlks];
__device__ float  g_es0_fin[kB];

// Self-resetting global barriers.
struct Bar { unsigned cnt; unsigned gen; };
__device__ Bar g_bars[4];

__device__ __forceinline__ void gbar(int id, unsigned nb) {
    __syncthreads();
    if (threadIdx.x == 0) {
        __threadfence();
        volatile unsigned* vgen = &g_bars[id].gen;
        unsigned g0 = *vgen;
        unsigned prev = atomicAdd(&g_bars[id].cnt, 1u);
        if (prev == nb - 1u) {
            g_bars[id].cnt = 0u;
            __threadfence();
            atomicAdd(&g_bars[id].gen, 1u);
        } else {
            while (*vgen == g0) { __nanosleep(64); }
            __threadfence();
        }
    }
    __syncthreads();
}

// ---------------------------------------------------------------------------
// helpers
// ---------------------------------------------------------------------------
__device__ __forceinline__ void ffma2(unsigned long long& d,
                                      unsigned long long a,
                                      unsigned long long b) {
    asm("fma.rn.f32x2 %0, %1, %2, %0;" : "+l"(d) : "l"(a), "l"(b));
}
__device__ __forceinline__ unsigned long long bcast2(float w) {
    unsigned long long r;
    asm("mov.b64 %0, {%1, %1};" : "=l"(r) : "f"(w));
    return r;
}
__device__ __forceinline__ float lo32(unsigned long long v) {
    return __uint_as_float((unsigned)(v & 0xffffffffull));
}
__device__ __forceinline__ float hi32(unsigned long long v) {
    return __uint_as_float((unsigned)(v >> 32));
}
__device__ __forceinline__ void cp_async16(float* sdst, const float* gsrc) {
    unsigned a = (unsigned)__cvta_generic_to_shared(sdst);
    asm volatile("cp.async.cg.shared.global [%0], [%1], 16;" :: "r"(a), "l"(gsrc));
}
#define CP_COMMIT() asm volatile("cp.async.commit_group;")
#define CP_WAIT1()  asm volatile("cp.async.wait_group 1;")

__device__ __forceinline__ void load16s(float d[16], const float* p) {
    const float4* p4 = (const float4*)p;
    float4 a = p4[0], b = p4[1], c = p4[2], e = p4[3];
    d[0]=a.x; d[1]=a.y; d[2]=a.z; d[3]=a.w;
    d[4]=b.x; d[5]=b.y; d[6]=b.z; d[7]=b.w;
    d[8]=c.x; d[9]=c.y; d[10]=c.z; d[11]=c.w;
    d[12]=e.x; d[13]=e.y; d[14]=e.z; d[15]=e.w;
}
__device__ __forceinline__ float4 ldcg4(const float* p) {
    return __ldcg((const float4*)p);
}
__device__ __forceinline__ float tree16(const float v[16]) {
    float a0=v[0]+v[1], a1=v[2]+v[3], a2=v[4]+v[5], a3=v[6]+v[7];
    float a4=v[8]+v[9], a5=v[10]+v[11], a6=v[12]+v[13], a7=v[14]+v[15];
    float b0=a0+a1, b1=a2+a3, b2=a4+a5, b3=a6+a7;
    return (b0+b1)+(b2+b3);
}
__device__ __forceinline__ float bfly16(float v) {
    v += __shfl_xor_sync(0xFFFFFFFFu, v, 1);
    v += __shfl_xor_sync(0xFFFFFFFFu, v, 2);
    v += __shfl_xor_sync(0xFFFFFFFFu, v, 4);
    v += __shfl_xor_sync(0xFFFFFFFFu, v, 8);
    return v;
}

// Stage one 32-row double-tile (16 rows from each k-half) into smem.
// 2688 float4 = exactly 4 per thread, coalesced.
__device__ __forceinline__ void stage_dtile(float* dst,
                                            const float* __restrict__ Wa,
                                            const float* __restrict__ Wsp,
                                            const float* __restrict__ Wst,
                                            int phys, int tid) {
#pragma unroll
    for (int h = 0; h < 4; h++) {
        int q = tid + h * kThreads;          // 0..2687
        int half = q / 1344;
        int rem  = q - half * 1344;
        int jj   = rem / 84;                 // row within 16-row subtile
        int col  = (rem % 84) * 4;
        int k = half * kKHalf + phys * kTileRows + jj;
        const float* src;
        if (col < 288)      src = Wa  + k * 288 + col;
        else if (col < 320) src = Wsp + k * 32 + (col - 288);
        else                src = Wst + k * 16 + (col - 320);
        cp_async16(dst + (half * kTileRows + jj) * kColsTot + col, src);
    }
}

// ---------------------------------------------------------------------------
// THE kernel
// ---------------------------------------------------------------------------
__global__ __launch_bounds__(kThreads) void fused_kernel(
    const float* __restrict__ s_i,
    const float* __restrict__ Wa,
    const float* __restrict__ Wsp,
    const float* __restrict__ Wst,
    const void* __restrict__ actions_raw,
    float* __restrict__ out) {
    extern __shared__ __align__(16) float smem[];
    float* smT  = smem + kOffT;
    float* smW  = smem + kOffW;
    float* sE0  = smem + kOffE0;
    float* sE1  = smem + kOffE1;
    float* sEs  = smem + kOffEs;
    float* sEa  = smem + kOffEa;
    double* red = (double*)(smem + kOffRed);
    __shared__ int s_is64;

    const int tid  = threadIdx.x;
    const int blk  = blockIdx.x;
    const int row0 = blk * kRowsPerBlk;

    // ---- Phase 1a: stage s_i transposed: smT[k*20 + r] ----
    if (tid == 0) {
        const unsigned* w = (const unsigned*)actions_raw;
        unsigned acc = 0;
#pragma unroll
        for (int j = 1; j < 64; j += 2) acc |= w[j];
        s_is64 = (acc == 0u) ? 1 : 0;
    }
    for (int idx = tid; idx < kRowsPerBlk * kS; idx += kThreads) {
        int r = idx >> 9;
        int k = idx & (kS - 1);
        int gr = row0 + r;
        smT[k * kTStride + r] = (gr <= kT) ? s_i[gr * kS + k] : 0.0f;
    }

    // ---- Phase 1b: GEMM ----
    // thread = (kh, rg, cg): k-half, row-half (8 rows), col pair (2 cols)
    const int kh = tid / 336;            // 0 or 1
    const int t2 = tid - kh * 336;
    const int rg = t2 / 168;             // 0 or 1
    const int cg = t2 - rg * 168;        // 0..167
    const int p0 = blk & (kNT - 1);

    stage_dtile(smW,       Wa, Wsp, Wst, (p0 + 0) & 15, tid);
    CP_COMMIT();
    stage_dtile(smW + kDT, Wa, Wsp, Wst, (p0 + 1) & 15, tid);
    CP_COMMIT();

    unsigned long long accA[4] = {0ull, 0ull, 0ull, 0ull};
    unsigned long long accB[4] = {0ull, 0ull, 0ull, 0ull};

    for (int i = 0; i < kNT; i++) {
        CP_WAIT1();
        __syncthreads();   // tile i visible; first iter also covers smT staging
        const int phys = (p0 + i) & 15;
        const float* wsub = smW + (i & 1) * kDT + kh * (kTileRows * kColsTot);
        const int kbase = kh * kKHalf + phys * kTileRows;
#pragma unroll
        for (int j = 0; j < kTileRows; j++) {
            float2 wv = *(const float2*)(wsub + j * kColsTot + 2 * cg);
            unsigned long long w2a = bcast2(wv.x);
            unsigned long long w2b = bcast2(wv.y);
            const ulonglong2* sp =
                (const ulonglong2*)(smT + (kbase + j) * kTStride + rg * 8);
            ulonglong2 q0 = sp[0];   // rows r0..r0+3 (two f32x2)
            ulonglong2 q1 = sp[1];   // rows r0+4..r0+7
            ffma2(accA[0], q0.x, w2a); ffma2(accB[0], q0.x, w2b);
            ffma2(accA[1], q0.y, w2a); ffma2(accB[1], q0.y, w2b);
            ffma2(accA[2], q1.x, w2a); ffma2(accB[2], q1.x, w2b);
            ffma2(accA[3], q1.y, w2a); ffma2(accB[3], q1.y, w2b);
        }
        __syncthreads();   // all reads of buffer (i&1) done
        if (i + 2 < kNT) {
            stage_dtile(smW + (i & 1) * kDT, Wa, Wsp, Wst,
                        (p0 + i + 2) & 15, tid);
            CP_COMMIT();
        }
    }

    // ---- Phase 1c: combine k-halves, write logits smL[r*336 + c] ----
    // kh=1 threads park their partials in smem; kh=0 threads add + store.
    unsigned long long* P = (unsigned long long*)smW;  // 336*8 ull = 21.5 KB
    if (kh == 1) {
#pragma unroll
        for (int p = 0; p < 4; p++) {
            P[t2 * 8 + p]     = accA[p];
            P[t2 * 8 + 4 + p] = accB[p];
        }
    }
    __syncthreads();
    float* smL = smT;  // reuse (all smT reads done)
    if (kh == 0) {
#pragma unroll
        for (int p = 0; p < 4; p++) {
            unsigned long long oA = P[t2 * 8 + p];
            unsigned long long oB = P[t2 * 8 + 4 + p];
            int r = rg * 8 + 2 * p;
            smL[(r    ) * kColsTot + 2 * cg    ] = lo32(accA[p]) + lo32(oA);
            smL[(r + 1) * kColsTot + 2 * cg    ] = hi32(accA[p]) + hi32(oA);
            smL[(r    ) * kColsTot + 2 * cg + 1] = lo32(accB[p]) + lo32(oB);
            smL[(r + 1) * kColsTot + 2 * cg + 1] = hi32(accB[p]) + hi32(oB);
        }
    }
    __syncthreads();

    // ---- Phase 1d: softmaxes (threads 0..255: r = tid>>4, b = tid&15) ----
    if (tid < 256) {
        const int r = tid >> 4;
        const int b = tid & 15;
        const int i = row0 + r;
        const bool valid = (i <= kT);
        const int is64 = s_is64;

        if (valid) {
            if (i < kT) {
                int a;
                if (is64) a = (int)((const long long*)actions_raw)[i];
                else      a = ((const int*)actions_raw)[i];
                const float* L = &smL[r * kColsTot + b * kA];
                float m = L[0];
#pragma unroll
                for (int j = 1; j < kA; j++) m = fmaxf(m, L[j]);
                float s = 0.0f;
#pragma unroll
                for (int j = 0; j < kA; j++) s += expf(L[j] - m);
                sEa[r * kB + b] = expf(L[a] - m) / s;
            }
            float x0 = smL[r * kColsTot + 288 + 2 * b];
            float x1 = smL[r * kColsTot + 288 + 2 * b + 1];
            float m = fmaxf(x0, x1);
            float e0 = expf(x0 - m), e1 = expf(x1 - m);
            float inv = 1.0f / (e0 + e1);
            float es0 = e0 * inv;
            sE0[r * kB + b] = es0;
            sE1[r * kB + b] = e1 * inv;
            if (i == kT) g_es0_fin[b] = es0;
        }
        {
            float x = smL[r * kColsTot + 320 + b];
            float m = x;
            m = fmaxf(m, __shfl_xor_sync(0xFFFFFFFFu, m, 1));
            m = fmaxf(m, __shfl_xor_sync(0xFFFFFFFFu, m, 2));
            m = fmaxf(m, __shfl_xor_sync(0xFFFFFFFFu, m, 4));
            m = fmaxf(m, __shfl_xor_sync(0xFFFFFFFFu, m, 8));
            float e = expf(x - m);
            float s = e;
            s += __shfl_xor_sync(0xFFFFFFFFu, s, 1);
            s += __shfl_xor_sync(0xFFFFFFFFu, s, 2);
            s += __shfl_xor_sync(0xFFFFFFFFu, s, 4);
            s += __shfl_xor_sync(0xFFFFFFFFu, s, 8);
            if (valid) sEs[r * kB + b] = e / s;
        }
    }
    __syncthreads();

    // ---- Phase 2: compose (warp 0 of blocks 0..127) ----
    if (blk < kNBlks && tid < 32) {
        const int k = tid & 15;
        float P16[16];
#pragma unroll
        for (int j = 0; j < 16; j++) P16[j] = (j == k) ? 1.0f : 0.0f;
        for (int s = 0; s < kBlkSteps; s++) {
            if (blk == 0 && s == 0) continue;
            float s0[16], s1[16], vv[16];
            load16s(s0, &sE0[s * kB]);
            load16s(s1, &sE1[s * kB]);
            load16s(vv, &sEs[s * kB]);
            float m[16];
#pragma unroll
            for (int j = 0; j < 16; j++) m[j] = s1[j] * P16[j];
            float w = tree16(m);
#pragma unroll
            for (int j = 0; j < 16; j++)
                P16[j] = fmaf(s0[j], P16[j], (vv[j] * EXP_NEG_PEN) * w);
        }
        if (tid < 16) {
#pragma unroll
            for (int j = 0; j < 16; j++)
                g_M[blk * 256 + j * 16 + k] = P16[j];
        }
    }

    gbar(0, kGrid);

    // ---- Phase 3: serial scan (block 0, warp 0), prefetch distance 2 ----
    if (blk == 0 && tid < 32) {
        const int r = tid & 15;
        float Q[16];
        load16s(Q, &sEs[0]);
        if (tid < 16) g_chk[tid] = Q[tid];
        if (tid == 0) g_Eb[0] = 0;
        int E = 0;

        float4 a0 = ldcg4(&g_M[0 * 256 + r * 16 + 0]);
        float4 a1 = ldcg4(&g_M[0 * 256 + r * 16 + 4]);
        float4 a2 = ldcg4(&g_M[0 * 256 + r * 16 + 8]);
        float4 a3 = ldcg4(&g_M[0 * 256 + r * 16 + 12]);
        float4 b0 = ldcg4(&g_M[1 * 256 + r * 16 + 0]);
        float4 b1 = ldcg4(&g_M[1 * 256 + r * 16 + 4]);
        float4 b2 = ldcg4(&g_M[1 * 256 + r * 16 + 8]);
        float4 b3 = ldcg4(&g_M[1 * 256 + r * 16 + 12]);

        for (int j = 0; j < kNBlks; j++) {
            float4 c0, c1, c2, c3;
            if (j + 2 < kNBlks) {
                const float* Mn = &g_M[(j + 2) * 256 + r * 16];
                c0 = ldcg4(Mn + 0); c1 = ldcg4(Mn + 4);
                c2 = ldcg4(Mn + 8); c3 = ldcg4(Mn + 12);
            }
            float mm[16] = {a0.x, a0.y, a0.z, a0.w, a1.x, a1.y, a1.z, a1.w,
                            a2.x, a2.y, a2.z, a2.w, a3.x, a3.y, a3.z, a3.w};
            float pr[16];
#pragma unroll
            for (int kk = 0; kk < 16; kk++) pr[kk] = mm[kk] * Q[kk];
            float outr = tree16(pr);

            float Qn[16];
#pragma unroll
            for (int kk = 0; kk < 16; kk++)
                Qn[kk] = __shfl_sync(0xFFFFFFFFu, outr, kk);

            float ss = tree16(Qn);
            int e = ((__float_as_int(ss) >> 23) & 0xFF) - 127;
            float sc = __int_as_float((127 - e) << 23);
#pragma unroll
            for (int kk = 0; kk < 16; kk++) Q[kk] = Qn[kk] * sc;
            E += e;

            if (tid < 16) g_chk[(j + 1) * kB + tid] = Q[tid];
            if (tid == 0) g_Eb[j + 1] = E;
            a0 = b0; a1 = b1; a2 = b2; a3 = b3;
            b0 = c0; b1 = c1; b2 = c2; b3 = c3;
        }
    }

    gbar(1, kGrid);

    // ---- Phase 4: replay ----
    if (blk < kNBlks && tid < 32) {
        const int b = tid & 15;
        float Q = __ldcg(&g_chk[blk * kB + b]);
        const int E = __ldcg(&g_Eb[blk]);
        double acc = 0.0;

#pragma unroll
        for (int s = 0; s < kBlkSteps; s++) {
            int idx = s * kB + b;
            float s0 = sE0[idx];
            float s1 = sE1[idx];
            float v  = sEs[idx] * EXP_NEG_PEN;
            float ea = sEa[idx];
            if (!(blk == 0 && s == 0)) {
                float t = bfly16(Q * s1);
                Q = fmaf(v, t, Q * s0);
            }
            float u = bfly16(Q * ea);
            acc += (double)logf(u);
        }
        acc += (double)(kBlkSteps * E) * LN2;

        if (blk == kNBlks - 1) {
            float u = bfly16(Q * __ldcg(&g_es0_fin[b]));
            acc += (double)logf(u) + (double)E * LN2;
        }
        if (tid == 0) g_part[blk] = acc;
    }

    gbar(2, kGrid);

    // ---- Phase 5: reduce (block 0) ----
    if (blk == 0) {
        if (tid < 128) red[tid] = __ldcg(&g_part[tid]);
        __syncthreads();
#pragma unroll
        for (int s = 64; s > 0; s >>= 1) {
            if (tid < s) red[tid] += red[tid + s];
            __syncthreads();
        }
        if (tid == 0) out[0] = (float)red[0];
    }
}

extern "C" void kernel_launch(void* const* d_in, const int* in_sizes, int n_in,
                              void* d_out, int out_size) {
    const float* s_i = (const float*)d_in[0];
    const float* Wa  = (const float*)d_in[1];
    const float* Wsp = (const float*)d_in[2];
    const float* Wst = (const float*)d_in[3];
    const void*  act = d_in[4];

    cudaFuncSetAttribute(fused_kernel,
                         cudaFuncAttributeMaxDynamicSharedMemorySize,
                         kSmemBytes);
    fused_kernel<<<kGrid, kThreads, kSmemBytes>>>(s_i, Wa, Wsp, Wst, act,
                                                  (float*)d_out);
}

// round 8
// speedup vs baseline: 7.3855x; 1.1225x over previous
#include <cuda_runtime.h>

typedef unsigned long long ull;

// ---------------------------------------------------------------------------
// Problem constants
// ---------------------------------------------------------------------------
namespace {
constexpr int kT = 2048;
constexpr int kS = 512;
constexpr int kB = 16;
constexpr int kA = 18;
constexpr int kColsTot = 336;           // 288 + 32 + 16
constexpr int kRowsPerBlk = 16;
constexpr int kBlkSteps = 16;
constexpr int kNBlks = kT / kBlkSteps;  // 128
constexpr int kGrid = 129;
constexpr int kThreads = 672;           // 4 kq x 2 rg x 84 cg
constexpr int kTStride = 20;            // padded row stride (words) for smT
constexpr int kTRows = 16;              // W rows per quarter per tile
constexpr int kNIt = 8;                 // 128 / 16 tile iterations
constexpr int kTileFloats = 4 * kTRows * kColsTot;  // 21504 (86 KB)
// dynamic smem layout (float offsets)
constexpr int kOffT   = 0;                        // smT: 512*20 = 10240
constexpr int kOffW   = 10240;                    // 2 tiles = 43008 floats
constexpr int kOffE0  = kOffW + 2 * kTileFloats;  // 53248
constexpr int kOffE1  = kOffE0 + 256;
constexpr int kOffEs  = kOffE1 + 256;
constexpr int kOffEa  = kOffEs + 256;
constexpr int kOffRed = kOffEa + 256;             // 8-byte aligned
constexpr int kSmemFloats = kOffRed + 256;        // 54528
constexpr int kSmemBytes = kSmemFloats * 4;       // 218112
// serial-phase M cache (in smW region): matrix stride 320 floats, row stride 20
constexpr int kMStrideRow = 20;
constexpr int kMStrideMat = 16 * kMStrideRow;     // 320
}
#define EXP_NEG_PEN 0.60653065971263342f
#define LN2 0.69314718055994530942

// Cross-block scratch.
__device__ float  g_M[kNBlks * kB * kB];
__device__ float  g_chk[(kNBlks + 1) * kB];
__device__ int    g_Eb[kNBlks + 1];
__device__ double g_part[kNBlks];
__device__ float  g_es0_fin[kB];

// Self-resetting global barriers.
struct Bar { unsigned cnt; unsigned gen; };
__device__ Bar g_bars[4];

__device__ __forceinline__ void gbar(int id, unsigned nb) {
    __syncthreads();
    if (threadIdx.x == 0) {
        __threadfence();
        volatile unsigned* vgen = &g_bars[id].gen;
        unsigned g0 = *vgen;
        unsigned prev = atomicAdd(&g_bars[id].cnt, 1u);
        if (prev == nb - 1u) {
            g_bars[id].cnt = 0u;
            __threadfence();
            atomicAdd(&g_bars[id].gen, 1u);
        } else {
            while (*vgen == g0) { __nanosleep(64); }
            __threadfence();
        }
    }
    __syncthreads();
}

// ---------------------------------------------------------------------------
// helpers
// ---------------------------------------------------------------------------
__device__ __forceinline__ void ffma2(ull& d, ull a, ull b) {
    asm("fma.rn.f32x2 %0, %1, %2, %0;" : "+l"(d) : "l"(a), "l"(b));
}
__device__ __forceinline__ ull bcast2(float w) {
    ull r;
    asm("mov.b64 %0, {%1, %1};" : "=l"(r) : "f"(w));
    return r;
}
__device__ __forceinline__ float lo32(ull v) {
    return __uint_as_float((unsigned)(v & 0xffffffffull));
}
__device__ __forceinline__ float hi32(ull v) {
    return __uint_as_float((unsigned)(v >> 32));
}
__device__ __forceinline__ void cp_async16(float* sdst, const float* gsrc) {
    unsigned a = (unsigned)__cvta_generic_to_shared(sdst);
    asm volatile("cp.async.cg.shared.global [%0], [%1], 16;" :: "r"(a), "l"(gsrc));
}
#define CP_COMMIT() asm volatile("cp.async.commit_group;")
#define CP_WAIT1()  asm volatile("cp.async.wait_group 1;")
#define CP_WAIT0()  asm volatile("cp.async.wait_group 0;")

__device__ __forceinline__ void load16s(float d[16], const float* p) {
    const float4* p4 = (const float4*)p;
    float4 a = p4[0], b = p4[1], c = p4[2], e = p4[3];
    d[0]=a.x; d[1]=a.y; d[2]=a.z; d[3]=a.w;
    d[4]=b.x; d[5]=b.y; d[6]=b.z; d[7]=b.w;
    d[8]=c.x; d[9]=c.y; d[10]=c.z; d[11]=c.w;
    d[12]=e.x; d[13]=e.y; d[14]=e.z; d[15]=e.w;
}
__device__ __forceinline__ float tree16(const float v[16]) {
    float a0=v[0]+v[1], a1=v[2]+v[3], a2=v[4]+v[5], a3=v[6]+v[7];
    float a4=v[8]+v[9], a5=v[10]+v[11], a6=v[12]+v[13], a7=v[14]+v[15];
    float b0=a0+a1, b1=a2+a3, b2=a4+a5, b3=a6+a7;
    return (b0+b1)+(b2+b3);
}
__device__ __forceinline__ float bfly16(float v) {
    v += __shfl_xor_sync(0xFFFFFFFFu, v, 1);
    v += __shfl_xor_sync(0xFFFFFFFFu, v, 2);
    v += __shfl_xor_sync(0xFFFFFFFFu, v, 4);
    v += __shfl_xor_sync(0xFFFFFFFFu, v, 8);
    return v;
}

// ---------------------------------------------------------------------------
// THE kernel
// ---------------------------------------------------------------------------
__global__ __launch_bounds__(kThreads) void fused_kernel(
    const float* __restrict__ s_i,
    const float* __restrict__ Wa,
    const float* __restrict__ Wsp,
    const float* __restrict__ Wst,
    const void* __restrict__ actions_raw,
    float* __restrict__ out) {
    extern __shared__ __align__(16) float smem[];
    float* smT  = smem + kOffT;
    float* smW  = smem + kOffW;
    float* sE0  = smem + kOffE0;
    float* sE1  = smem + kOffE1;
    float* sEs  = smem + kOffEs;
    float* sEa  = smem + kOffEa;
    double* red = (double*)(smem + kOffRed);
    __shared__ int s_is64;

    const int tid  = threadIdx.x;
    const int blk  = blockIdx.x;
    const int row0 = blk * kRowsPerBlk;

    // ---- Phase 1a: stage s_i transposed: smT[k*20 + r] ----
    if (tid == 0) {
        const unsigned* w = (const unsigned*)actions_raw;
        unsigned acc = 0;
#pragma unroll
        for (int j = 1; j < 64; j += 2) acc |= w[j];
        s_is64 = (acc == 0u) ? 1 : 0;
    }
    for (int idx = tid; idx < kRowsPerBlk * kS; idx += kThreads) {
        int r = idx >> 9;
        int k = idx & (kS - 1);
        int gr = row0 + r;
        smT[k * kTStride + r] = (gr <= kT) ? s_i[gr * kS + k] : 0.0f;
    }

    // ---- Phase 1b: GEMM ----
    // thread = (kq, rg, cg): k-quarter (128 k's), row-half (8 rows), col-quad
    const int kq = tid / 168;
    const int tp = tid - kq * 168;
    const int rg = tp / 84;
    const int cg = tp - rg * 84;
    const int p0 = blk & 7;

    // division-free staging descriptor: thread stages rows {rg, rg+2, .., rg+14}
    // of its quarter's tile at its fixed 4-column group.
    const float* wptr; int wstride;
    {
        int col = cg * 4;
        if (col < 288)      { wptr = Wa  + col;         wstride = 288; }
        else if (col < 320) { wptr = Wsp + (col - 288); wstride = 32; }
        else                { wptr = Wst + (col - 320); wstride = 16; }
    }
    const int kq128a  = kq * 128 + rg;
    const int dstbase = (kq * 16 + rg) * kColsTot + cg * 4;

    // prestage tiles 0 and 1
    {
        float* d0 = smW;
        float* d1 = smW + kTileFloats;
#pragma unroll
        for (int h = 0; h < 8; h++) {
            int k = kq128a + (p0 & 7) * 16 + 2 * h;
            cp_async16(d0 + dstbase + 2 * h * kColsTot, wptr + k * wstride);
        }
        CP_COMMIT();
#pragma unroll
        for (int h = 0; h < 8; h++) {
            int k = kq128a + ((p0 + 1) & 7) * 16 + 2 * h;
            cp_async16(d1 + dstbase + 2 * h * kColsTot, wptr + k * wstride);
        }
        CP_COMMIT();
    }

    ull accs[16];
#pragma unroll
    for (int p = 0; p < 16; p++) accs[p] = 0ull;

    for (int i = 0; i < kNIt; i++) {
        CP_WAIT1();
        __syncthreads();   // tile i visible; first iter also covers smT staging
        const int phys = (p0 + i) & 7;
        const float* wsub = smW + (i & 1) * kTileFloats + kq * (kTRows * kColsTot);
        const int kbase = kq * 128 + phys * 16;
#pragma unroll
        for (int j = 0; j < kTRows; j++) {
            float4 w4 = *(const float4*)(wsub + j * kColsTot + 4 * cg);
            ull wa2 = bcast2(w4.x);
            ull wb2 = bcast2(w4.y);
            ull wc2 = bcast2(w4.z);
            ull wd2 = bcast2(w4.w);
            const ulonglong2* sp =
                (const ulonglong2*)(smT + (kbase + j) * kTStride + rg * 8);
            ulonglong2 q0 = sp[0];
            ulonglong2 q1 = sp[1];
            ffma2(accs[0],  q0.x, wa2); ffma2(accs[1],  q0.y, wa2);
            ffma2(accs[2],  q1.x, wa2); ffma2(accs[3],  q1.y, wa2);
            ffma2(accs[4],  q0.x, wb2); ffma2(accs[5],  q0.y, wb2);
            ffma2(accs[6],  q1.x, wb2); ffma2(accs[7],  q1.y, wb2);
            ffma2(accs[8],  q0.x, wc2); ffma2(accs[9],  q0.y, wc2);
            ffma2(accs[10], q1.x, wc2); ffma2(accs[11], q1.y, wc2);
            ffma2(accs[12], q0.x, wd2); ffma2(accs[13], q0.y, wd2);
            ffma2(accs[14], q1.x, wd2); ffma2(accs[15], q1.y, wd2);
        }
        __syncthreads();   // all reads of buffer (i&1) done
        if (i + 2 < kNIt) {
            float* d = smW + (i & 1) * kTileFloats;
            const int ph2 = (p0 + i + 2) & 7;
#pragma unroll
            for (int h = 0; h < 8; h++) {
                int k = kq128a + ph2 * 16 + 2 * h;
                cp_async16(d + dstbase + 2 * h * kColsTot, wptr + k * wstride);
            }
            CP_COMMIT();
        }
    }

    // ---- Phase 1c: combine 4 k-quarters -> logits smL[r*336 + c] ----
    ull* P = (ull*)smW;  // 3*168*16 ull = 64.5 KB (tile data all consumed)
    if (kq > 0) {
#pragma unroll
        for (int p = 0; p < 16; p++)
            P[((kq - 1) * 168 + tp) * 16 + p] = accs[p];
    }
    __syncthreads();
    float* smL = smT;  // reuse (all smT reads done)
    if (kq == 0) {
#pragma unroll
        for (int c = 0; c < 4; c++) {
#pragma unroll
            for (int p = 0; p < 4; p++) {
                float lo = lo32(accs[c * 4 + p]);
                float hi = hi32(accs[c * 4 + p]);
#pragma unroll
                for (int s = 0; s < 3; s++) {
                    ull o = P[(s * 168 + tp) * 16 + c * 4 + p];
                    lo += lo32(o);
                    hi += hi32(o);
                }
                int r = rg * 8 + 2 * p;
                smL[(r    ) * kColsTot + cg * 4 + c] = lo;
                smL[(r + 1) * kColsTot + cg * 4 + c] = hi;
            }
        }
    }
    __syncthreads();

    // ---- Phase 1d: softmaxes (threads 0..255: r = tid>>4, b = tid&15) ----
    if (tid < 256) {
        const int r = tid >> 4;
        const int b = tid & 15;
        const int i = row0 + r;
        const bool valid = (i <= kT);
        const int is64 = s_is64;

        if (valid) {
            if (i < kT) {
                int a;
                if (is64) a = (int)((const long long*)actions_raw)[i];
                else      a = ((const int*)actions_raw)[i];
                const float* L = &smL[r * kColsTot + b * kA];
                float m = L[0];
#pragma unroll
                for (int j = 1; j < kA; j++) m = fmaxf(m, L[j]);
                float s = 0.0f;
#pragma unroll
                for (int j = 0; j < kA; j++) s += expf(L[j] - m);
                sEa[r * kB + b] = expf(L[a] - m) / s;
            }
            float x0 = smL[r * kColsTot + 288 + 2 * b];
            float x1 = smL[r * kColsTot + 288 + 2 * b + 1];
            float m = fmaxf(x0, x1);
            float e0 = expf(x0 - m), e1 = expf(x1 - m);
            float inv = 1.0f / (e0 + e1);
            float es0 = e0 * inv;
            sE0[r * kB + b] = es0;
            sE1[r * kB + b] = e1 * inv;
            if (i == kT) g_es0_fin[b] = es0;
        }
        {
            float x = smL[r * kColsTot + 320 + b];
            float m = x;
            m = fmaxf(m, __shfl_xor_sync(0xFFFFFFFFu, m, 1));
            m = fmaxf(m, __shfl_xor_sync(0xFFFFFFFFu, m, 2));
            m = fmaxf(m, __shfl_xor_sync(0xFFFFFFFFu, m, 4));
            m = fmaxf(m, __shfl_xor_sync(0xFFFFFFFFu, m, 8));
            float e = expf(x - m);
            float s = e;
            s += __shfl_xor_sync(0xFFFFFFFFu, s, 1);
            s += __shfl_xor_sync(0xFFFFFFFFu, s, 2);
            s += __shfl_xor_sync(0xFFFFFFFFu, s, 4);
            s += __shfl_xor_sync(0xFFFFFFFFu, s, 8);
            if (valid) sEs[r * kB + b] = e / s;
        }
    }
    __syncthreads();

    // ---- Phase 2: compose (warp 0 of blocks 0..127) ----
    if (blk < kNBlks && tid < 32) {
        const int k = tid & 15;
        float P16[16];
#pragma unroll
        for (int j = 0; j < 16; j++) P16[j] = (j == k) ? 1.0f : 0.0f;
        for (int s = 0; s < kBlkSteps; s++) {
            if (blk == 0 && s == 0) continue;
            float s0[16], s1[16], vv[16];
            load16s(s0, &sE0[s * kB]);
            load16s(s1, &sE1[s * kB]);
            load16s(vv, &sEs[s * kB]);
            float m[16];
#pragma unroll
            for (int j = 0; j < 16; j++) m[j] = s1[j] * P16[j];
            float w = tree16(m);
#pragma unroll
            for (int j = 0; j < 16; j++)
                P16[j] = fmaf(s0[j], P16[j], (vv[j] * EXP_NEG_PEN) * w);
        }
        if (tid < 16) {
#pragma unroll
            for (int j = 0; j < 16; j++)
                g_M[blk * 256 + j * 16 + k] = P16[j];
        }
    }

    gbar(0, kGrid);  // all g_M + g_es0_fin visible

    // ---- Phase 3: serial scan (block 0): preload M into smem, then 1 warp ----
    if (blk == 0) {
        float* smM = smW;  // 128 matrices, padded: 320 floats each = 160 KB
#pragma unroll
        for (int h = 0; h < 13; h++) {
            int q = tid + h * kThreads;
            if (q < 8192) {          // 8192 16B-chunks = 128*16*4
                int m   = q >> 6;
                int rem = q & 63;
                int row = rem >> 2;
                int ch  = rem & 3;
                cp_async16(smM + m * kMStrideMat + row * kMStrideRow + ch * 4,
                           (const float*)g_M + q * 4);
            }
        }
        CP_COMMIT();
        CP_WAIT0();
        __syncthreads();

        if (tid < 32) {
            const int r = tid & 15;
            float Q[16];
            load16s(Q, &sEs[0]);
            if (tid < 16) g_chk[tid] = Q[tid];
            if (tid == 0) g_Eb[0] = 0;
            int E = 0;

            const float* Mr = smM + r * kMStrideRow;
            float4 a0 = *(const float4*)(Mr + 0);
            float4 a1 = *(const float4*)(Mr + 4);
            float4 a2 = *(const float4*)(Mr + 8);
            float4 a3 = *(const float4*)(Mr + 12);

            for (int j = 0; j < kNBlks; j++) {
                float4 b0, b1, b2, b3;
                if (j + 1 < kNBlks) {
                    const float* Mn = smM + (j + 1) * kMStrideMat + r * kMStrideRow;
                    b0 = *(const float4*)(Mn + 0);
                    b1 = *(const float4*)(Mn + 4);
                    b2 = *(const float4*)(Mn + 8);
                    b3 = *(const float4*)(Mn + 12);
                }
                float mm[16] = {a0.x, a0.y, a0.z, a0.w, a1.x, a1.y, a1.z, a1.w,
                                a2.x, a2.y, a2.z, a2.w, a3.x, a3.y, a3.z, a3.w};
                float pr[16];
#pragma unroll
                for (int kk = 0; kk < 16; kk++) pr[kk] = mm[kk] * Q[kk];
                float outr = tree16(pr);

                float Qn[16];
#pragma unroll
                for (int kk = 0; kk < 16; kk++)
                    Qn[kk] = __shfl_sync(0xFFFFFFFFu, outr, kk);

                float ss = tree16(Qn);
                int e = ((__float_as_int(ss) >> 23) & 0xFF) - 127;
                float sc = __int_as_float((127 - e) << 23);
#pragma unroll
                for (int kk = 0; kk < 16; kk++) Q[kk] = Qn[kk] * sc;
                E += e;

                if (tid < 16) g_chk[(j + 1) * kB + tid] = Q[tid];
                if (tid == 0) g_Eb[j + 1] = E;
                a0 = b0; a1 = b1; a2 = b2; a3 = b3;
            }
        }
    }

    gbar(1, kGrid);  // checkpoints ready

    // ---- Phase 4: replay ----
    if (blk < kNBlks && tid < 32) {
        const int b = tid & 15;
        float Q = __ldcg(&g_chk[blk * kB + b]);
        const int E = __ldcg(&g_Eb[blk]);
        double acc = 0.0;

#pragma unroll
        for (int s = 0; s < kBlkSteps; s++) {
            int idx = s * kB + b;
            float s0 = sE0[idx];
            float s1 = sE1[idx];
            float v  = sEs[idx] * EXP_NEG_PEN;
            float ea = sEa[idx];
            if (!(blk == 0 && s == 0)) {
                float t = bfly16(Q * s1);
                Q = fmaf(v, t, Q * s0);
            }
            float u = bfly16(Q * ea);
            acc += (double)logf(u);
        }
        acc += (double)(kBlkSteps * E) * LN2;

        if (blk == kNBlks - 1) {
            float u = bfly16(Q * __ldcg(&g_es0_fin[b]));
            acc += (double)logf(u) + (double)E * LN2;
        }
        if (tid == 0) g_part[blk] = acc;
    }

    gbar(2, kGrid);  // partials ready

    // ---- Phase 5: reduce (block 0) ----
    if (blk == 0) {
        if (tid < 128) red[tid] = __ldcg(&g_part[tid]);
        __syncthreads();
#pragma unroll
        for (int s = 64; s > 0; s >>= 1) {
            if (tid < s) red[tid] += red[tid + s];
            __syncthreads();
        }
        if (tid == 0) out[0] = (float)red[0];
    }
}

extern "C" void kernel_launch(void* const* d_in, const int* in_sizes, int n_in,
                              void* d_out, int out_size) {
    const float* s_i = (const float*)d_in[0];
    const float* Wa  = (const float*)d_in[1];
    const float* Wsp = (const float*)d_in[2];
    const float* Wst = (const float*)d_in[3];
    const void*  act = d_in[4];

    cudaFuncSetAttribute(fused_kernel,
                         cudaFuncAttributeMaxDynamicSharedMemorySize,
                         kSmemBytes);
    fused_kernel<<<kGrid, kThreads, kSmemBytes>>>(s_i, Wa, Wsp, Wst, act,
                                                  (float*)d_out);
}

// round 9
// speedup vs baseline: 9.0571x; 1.2263x over previous
#include <cuda_runtime.h>

typedef unsigned long long ull;

// ---------------------------------------------------------------------------
// Problem constants
// ---------------------------------------------------------------------------
namespace {
constexpr int kT = 2048;
constexpr int kS = 512;
constexpr int kB = 16;
constexpr int kA = 18;
constexpr int kColsTot = 336;             // 288 + 32 + 16
constexpr int kRowsPerBlk = 16;
constexpr int kBlkSteps = 16;
constexpr int kNBlks = kT / kBlkSteps;    // 128
constexpr int kGrid = 129;
constexpr int kThreads = 672;             // 21 warps
constexpr int kAStride = 516;             // smA row stride (conflict-free frags)
constexpr int kWStride = 340;             // W tile row stride (conflict-free frags)
constexpr int kTileK = 64;                // k-rows per W tile
constexpr int kNIt = kS / kTileK;         // 8 tiles
constexpr int kWTileFloats = kTileK * kWStride;  // 21760
// dynamic smem layout (float offsets)
constexpr int kOffA   = 0;                         // 16*516 = 8256
constexpr int kOffW   = 8256;                      // 2 tiles = 43520
constexpr int kOffL   = kOffW;                     // logits alias W buf0 (after GEMM)
constexpr int kOffE0  = kOffW + 2 * kWTileFloats;  // 51776
constexpr int kOffE1  = kOffE0 + 256;
constexpr int kOffEs  = kOffE1 + 256;
constexpr int kOffEa  = kOffEs + 256;
constexpr int kOffRed = kOffEa + 256;              // 52800 (byte 211200, 8-aligned)
constexpr int kSmemFloats = kOffRed + 256;
constexpr int kSmemBytes = kSmemFloats * 4;        // 212224
// serial-phase M cache (in smW region)
constexpr int kMStrideRow = 20;
constexpr int kMStrideMat = 16 * kMStrideRow;      // 320
}
#define EXP_NEG_PEN 0.60653065971263342f
#define LN2 0.69314718055994530942

// Cross-block scratch.
__device__ float  g_M[kNBlks * kB * kB];
__device__ float  g_chk[(kNBlks + 1) * kB];
__device__ int    g_Eb[kNBlks + 1];
__device__ double g_part[kNBlks];
__device__ float  g_es0_fin[kB];

// Self-resetting global barriers.
struct Bar { unsigned cnt; unsigned gen; };
__device__ Bar g_bars[4];

__device__ __forceinline__ void gbar(int id, unsigned nb) {
    __syncthreads();
    if (threadIdx.x == 0) {
        __threadfence();
        volatile unsigned* vgen = &g_bars[id].gen;
        unsigned g0 = *vgen;
        unsigned prev = atomicAdd(&g_bars[id].cnt, 1u);
        if (prev == nb - 1u) {
            g_bars[id].cnt = 0u;
            __threadfence();
            atomicAdd(&g_bars[id].gen, 1u);
        } else {
            while (*vgen == g0) { __nanosleep(64); }
            __threadfence();
        }
    }
    __syncthreads();
}

// ---------------------------------------------------------------------------
// helpers
// ---------------------------------------------------------------------------
__device__ __forceinline__ void cp_async16(float* sdst, const float* gsrc) {
    unsigned a = (unsigned)__cvta_generic_to_shared(sdst);
    asm volatile("cp.async.cg.shared.global [%0], [%1], 16;" :: "r"(a), "l"(gsrc));
}
__device__ __forceinline__ void cp_async16z(float* sdst, const float* gsrc,
                                            int srcbytes) {
    unsigned a = (unsigned)__cvta_generic_to_shared(sdst);
    asm volatile("cp.async.cg.shared.global [%0], [%1], 16, %2;"
                 :: "r"(a), "l"(gsrc), "r"(srcbytes));
}
#define CP_COMMIT() asm volatile("cp.async.commit_group;")
#define CP_WAIT1()  asm volatile("cp.async.wait_group 1;")
#define CP_WAIT0()  asm volatile("cp.async.wait_group 0;")

__device__ __forceinline__ unsigned cvt_tf32(float x) {
    unsigned r;
    asm("cvt.rna.tf32.f32 %0, %1;" : "=r"(r) : "f"(x));
    return r;
}
__device__ __forceinline__ void mma_tf32(float c[4], const unsigned a[4],
                                         const unsigned b[2]) {
    asm("mma.sync.aligned.m16n8k8.row.col.f32.tf32.tf32.f32 "
        "{%0,%1,%2,%3}, {%4,%5,%6,%7}, {%8,%9}, {%0,%1,%2,%3};"
        : "+f"(c[0]), "+f"(c[1]), "+f"(c[2]), "+f"(c[3])
        : "r"(a[0]), "r"(a[1]), "r"(a[2]), "r"(a[3]), "r"(b[0]), "r"(b[1]));
}

__device__ __forceinline__ void load16s(float d[16], const float* p) {
    const float4* p4 = (const float4*)p;
    float4 a = p4[0], b = p4[1], c = p4[2], e = p4[3];
    d[0]=a.x; d[1]=a.y; d[2]=a.z; d[3]=a.w;
    d[4]=b.x; d[5]=b.y; d[6]=b.z; d[7]=b.w;
    d[8]=c.x; d[9]=c.y; d[10]=c.z; d[11]=c.w;
    d[12]=e.x; d[13]=e.y; d[14]=e.z; d[15]=e.w;
}
__device__ __forceinline__ float tree16(const float v[16]) {
    float a0=v[0]+v[1], a1=v[2]+v[3], a2=v[4]+v[5], a3=v[6]+v[7];
    float a4=v[8]+v[9], a5=v[10]+v[11], a6=v[12]+v[13], a7=v[14]+v[15];
    float b0=a0+a1, b1=a2+a3, b2=a4+a5, b3=a6+a7;
    return (b0+b1)+(b2+b3);
}
__device__ __forceinline__ float bfly16(float v) {
    v += __shfl_xor_sync(0xFFFFFFFFu, v, 1);
    v += __shfl_xor_sync(0xFFFFFFFFu, v, 2);
    v += __shfl_xor_sync(0xFFFFFFFFu, v, 4);
    v += __shfl_xor_sync(0xFFFFFFFFu, v, 8);
    return v;
}

// ---------------------------------------------------------------------------
// THE kernel
// ---------------------------------------------------------------------------
__global__ __launch_bounds__(kThreads) void fused_kernel(
    const float* __restrict__ s_i,
    const float* __restrict__ Wa,
    const float* __restrict__ Wsp,
    const float* __restrict__ Wst,
    const void* __restrict__ actions_raw,
    float* __restrict__ out) {
    extern __shared__ __align__(16) float smem[];
    float* smA  = smem + kOffA;
    float* smW  = smem + kOffW;
    float* smL  = smem + kOffL;
    float* sE0  = smem + kOffE0;
    float* sE1  = smem + kOffE1;
    float* sEs  = smem + kOffEs;
    float* sEa  = smem + kOffEa;
    double* red = (double*)(smem + kOffRed);
    __shared__ int s_is64;

    const int tid  = threadIdx.x;
    const int blk  = blockIdx.x;
    const int row0 = blk * kRowsPerBlk;

    if (tid == 0) {
        const unsigned* w = (const unsigned*)actions_raw;
        unsigned acc = 0;
#pragma unroll
        for (int j = 1; j < 64; j += 2) acc |= w[j];
        s_is64 = (acc == 0u) ? 1 : 0;
    }

    // ---- Phase 1a: stage A (s_i rows, row-major, stride 516) via cp.async ----
    // 2048 16B chunks; OOB rows (block 128 tail) zero-filled via src-size 0.
#pragma unroll
    for (int h = 0; h < 4; h++) {
        int q = tid + h * kThreads;
        if (q < 2048) {
            int r  = q >> 7;           // 128 chunks per row
            int kc = (q & 127) * 4;
            int gr = row0 + r;
            bool ok = (gr <= kT);
            const float* src = ok ? (s_i + gr * kS + kc) : s_i;
            cp_async16z(smA + r * kAStride + kc, src, ok ? 16 : 0);
        }
    }

    // ---- W staging setup: thread = (rowgrp = tid/84, cg = tid%84) ----
    const int srg = tid / 84;          // 0..7
    const int scg = tid - srg * 84;    // 0..83
    const float* wptr; int wstride;
    {
        int col = scg * 4;
        if (col < 288)      { wptr = Wa  + col;         wstride = 288; }
        else if (col < 320) { wptr = Wsp + (col - 288); wstride = 32; }
        else                { wptr = Wst + (col - 320); wstride = 16; }
    }
    const int p0 = blk & (kNIt - 1);

    // prestage tiles 0 (grouped with A) and 1
    {
        float* d0 = smW;
#pragma unroll
        for (int h = 0; h < 8; h++) {
            int row = srg + 8 * h;
            int k = p0 * kTileK + row;
            cp_async16(d0 + row * kWStride + scg * 4, wptr + k * wstride);
        }
        CP_COMMIT();   // group: A + tile0
        float* d1 = smW + kWTileFloats;
        const int ph1 = (p0 + 1) & (kNIt - 1);
#pragma unroll
        for (int h = 0; h < 8; h++) {
            int row = srg + 8 * h;
            int k = ph1 * kTileK + row;
            cp_async16(d1 + row * kWStride + scg * 4, wptr + k * wstride);
        }
        CP_COMMIT();   // group: tile1
    }

    // ---- Phase 1b: tensor-core GEMM (tf32 m16n8k8) ----
    const int lane = tid & 31;
    const int wid  = tid >> 5;         // 0..20
    const int g    = lane >> 2;        // fragment row group
    const int t    = lane & 3;         // fragment k/col-in-group
    const int cb0  = wid * 16;         // col-tile 0 base
    const int cb1  = cb0 + 8;
    const int bcol = lane >> 2;        // B fragment column

    float c0[4] = {0.f, 0.f, 0.f, 0.f};
    float c1[4] = {0.f, 0.f, 0.f, 0.f};

    for (int i = 0; i < kNIt; i++) {
        CP_WAIT1();
        __syncthreads();               // tile i (+A on i==0) visible
        const int phys = (p0 + i) & (kNIt - 1);
        const float* wt = smW + (i & 1) * kWTileFloats;
        const int kbase = phys * kTileK;
#pragma unroll
        for (int kk = 0; kk < 8; kk++) {
            const int k0 = kbase + kk * 8;
            unsigned a[4];
            a[0] = cvt_tf32(smA[(g    ) * kAStride + k0 + t    ]);
            a[1] = cvt_tf32(smA[(g + 8) * kAStride + k0 + t    ]);
            a[2] = cvt_tf32(smA[(g    ) * kAStride + k0 + t + 4]);
            a[3] = cvt_tf32(smA[(g + 8) * kAStride + k0 + t + 4]);
            const int br = kk * 8 + t;
            unsigned b0[2], b1[2];
            b0[0] = cvt_tf32(wt[(br    ) * kWStride + cb0 + bcol]);
            b0[1] = cvt_tf32(wt[(br + 4) * kWStride + cb0 + bcol]);
            b1[0] = cvt_tf32(wt[(br    ) * kWStride + cb1 + bcol]);
            b1[1] = cvt_tf32(wt[(br + 4) * kWStride + cb1 + bcol]);
            mma_tf32(c0, a, b0);
            mma_tf32(c1, a, b1);
        }
        __syncthreads();               // all reads of buffer (i&1) done
        if (i + 2 < kNIt) {
            float* d = smW + (i & 1) * kWTileFloats;
            const int ph2 = (p0 + i + 2) & (kNIt - 1);
#pragma unroll
            for (int h = 0; h < 8; h++) {
                int row = srg + 8 * h;
                int k = ph2 * kTileK + row;
                cp_async16(d + row * kWStride + scg * 4, wptr + k * wstride);
            }
            CP_COMMIT();
        }
    }

    // ---- Phase 1c: epilogue — scatter C fragments to smL[r*336 + c] ----
    // (smL aliases W buffer 0; last compute used buffer 1, sync above protects)
    {
        int col0 = cb0 + 2 * t;
        smL[(g    ) * kColsTot + col0    ] = c0[0];
        smL[(g    ) * kColsTot + col0 + 1] = c0[1];
        smL[(g + 8) * kColsTot + col0    ] = c0[2];
        smL[(g + 8) * kColsTot + col0 + 1] = c0[3];
        int col1 = cb1 + 2 * t;
        smL[(g    ) * kColsTot + col1    ] = c1[0];
        smL[(g    ) * kColsTot + col1 + 1] = c1[1];
        smL[(g + 8) * kColsTot + col1    ] = c1[2];
        smL[(g + 8) * kColsTot + col1 + 1] = c1[3];
    }
    __syncthreads();

    // ---- Phase 1d: softmaxes (threads 0..255: r = tid>>4, b = tid&15) ----
    if (tid < 256) {
        const int r = tid >> 4;
        const int b = tid & 15;
        const int i = row0 + r;
        const bool valid = (i <= kT);
        const int is64 = s_is64;

        if (valid) {
            if (i < kT) {
                int a;
                if (is64) a = (int)((const long long*)actions_raw)[i];
                else      a = ((const int*)actions_raw)[i];
                const float* L = &smL[r * kColsTot + b * kA];
                float m = L[0];
#pragma unroll
                for (int j = 1; j < kA; j++) m = fmaxf(m, L[j]);
                float s = 0.0f;
#pragma unroll
                for (int j = 0; j < kA; j++) s += expf(L[j] - m);
                sEa[r * kB + b] = expf(L[a] - m) / s;
            }
            float x0 = smL[r * kColsTot + 288 + 2 * b];
            float x1 = smL[r * kColsTot + 288 + 2 * b + 1];
            float m = fmaxf(x0, x1);
            float e0 = expf(x0 - m), e1 = expf(x1 - m);
            float inv = 1.0f / (e0 + e1);
            float es0 = e0 * inv;
            sE0[r * kB + b] = es0;
            sE1[r * kB + b] = e1 * inv;
            if (i == kT) g_es0_fin[b] = es0;
        }
        {
            float x = smL[r * kColsTot + 320 + b];
            float m = x;
            m = fmaxf(m, __shfl_xor_sync(0xFFFFFFFFu, m, 1));
            m = fmaxf(m, __shfl_xor_sync(0xFFFFFFFFu, m, 2));
            m = fmaxf(m, __shfl_xor_sync(0xFFFFFFFFu, m, 4));
            m = fmaxf(m, __shfl_xor_sync(0xFFFFFFFFu, m, 8));
            float e = expf(x - m);
            float s = e;
            s += __shfl_xor_sync(0xFFFFFFFFu, s, 1);
            s += __shfl_xor_sync(0xFFFFFFFFu, s, 2);
            s += __shfl_xor_sync(0xFFFFFFFFu, s, 4);
            s += __shfl_xor_sync(0xFFFFFFFFu, s, 8);
            if (valid) sEs[r * kB + b] = e / s;
        }
    }
    __syncthreads();

    // ---- Phase 2: compose (warp 0 of blocks 0..127) ----
    if (blk < kNBlks && tid < 32) {
        const int k = tid & 15;
        float P16[16];
#pragma unroll
        for (int j = 0; j < 16; j++) P16[j] = (j == k) ? 1.0f : 0.0f;
        for (int s = 0; s < kBlkSteps; s++) {
            if (blk == 0 && s == 0) continue;
            float s0[16], s1[16], vv[16];
            load16s(s0, &sE0[s * kB]);
            load16s(s1, &sE1[s * kB]);
            load16s(vv, &sEs[s * kB]);
            float m[16];
#pragma unroll
            for (int j = 0; j < 16; j++) m[j] = s1[j] * P16[j];
            float w = tree16(m);
#pragma unroll
            for (int j = 0; j < 16; j++)
                P16[j] = fmaf(s0[j], P16[j], (vv[j] * EXP_NEG_PEN) * w);
        }
        if (tid < 16) {
#pragma unroll
            for (int j = 0; j < 16; j++)
                g_M[blk * 256 + j * 16 + k] = P16[j];
        }
    }

    gbar(0, kGrid);  // all g_M + g_es0_fin visible

    // ---- Phase 3: serial scan (block 0): preload M to smem, then 1 warp ----
    if (blk == 0) {
        float* smM = smW;  // 128 matrices, padded: 320 floats each
#pragma unroll
        for (int h = 0; h < 13; h++) {
            int q = tid + h * kThreads;
            if (q < 8192) {
                int m   = q >> 6;
                int rem = q & 63;
                int row = rem >> 2;
                int ch  = rem & 3;
                cp_async16(smM + m * kMStrideMat + row * kMStrideRow + ch * 4,
                           (const float*)g_M + q * 4);
            }
        }
        CP_COMMIT();
        CP_WAIT0();
        __syncthreads();

        if (tid < 32) {
            const int r = tid & 15;
            float Q[16];
            load16s(Q, &sEs[0]);
            if (tid < 16) g_chk[tid] = Q[tid];
            if (tid == 0) g_Eb[0] = 0;
            int E = 0;

            const float* Mr = smM + r * kMStrideRow;
            float4 a0 = *(const float4*)(Mr + 0);
            float4 a1 = *(const float4*)(Mr + 4);
            float4 a2 = *(const float4*)(Mr + 8);
            float4 a3 = *(const float4*)(Mr + 12);

            for (int j = 0; j < kNBlks; j++) {
                float4 b0, b1, b2, b3;
                if (j + 1 < kNBlks) {
                    const float* Mn = smM + (j + 1) * kMStrideMat + r * kMStrideRow;
                    b0 = *(const float4*)(Mn + 0);
                    b1 = *(const float4*)(Mn + 4);
                    b2 = *(const float4*)(Mn + 8);
                    b3 = *(const float4*)(Mn + 12);
                }
                float mm[16] = {a0.x, a0.y, a0.z, a0.w, a1.x, a1.y, a1.z, a1.w,
                                a2.x, a2.y, a2.z, a2.w, a3.x, a3.y, a3.z, a3.w};
                float pr[16];
#pragma unroll
                for (int kk = 0; kk < 16; kk++) pr[kk] = mm[kk] * Q[kk];
                float outr = tree16(pr);

                float Qn[16];
#pragma unroll
                for (int kk = 0; kk < 16; kk++)
                    Qn[kk] = __shfl_sync(0xFFFFFFFFu, outr, kk);

                float ss = tree16(Qn);
                int e = ((__float_as_int(ss) >> 23) & 0xFF) - 127;
                float sc = __int_as_float((127 - e) << 23);
#pragma unroll
                for (int kk = 0; kk < 16; kk++) Q[kk] = Qn[kk] * sc;
                E += e;

                if (tid < 16) g_chk[(j + 1) * kB + tid] = Q[tid];
                if (tid == 0) g_Eb[j + 1] = E;
                a0 = b0; a1 = b1; a2 = b2; a3 = b3;
            }
        }
    }

    gbar(1, kGrid);  // checkpoints ready

    // ---- Phase 4: replay ----
    if (blk < kNBlks && tid < 32) {
        const int b = tid & 15;
        float Q = __ldcg(&g_chk[blk * kB + b]);
        const int E = __ldcg(&g_Eb[blk]);
        double acc = 0.0;

#pragma unroll
        for (int s = 0; s < kBlkSteps; s++) {
            int idx = s * kB + b;
            float s0 = sE0[idx];
            float s1 = sE1[idx];
            float v  = sEs[idx] * EXP_NEG_PEN;
            float ea = sEa[idx];
            if (!(blk == 0 && s == 0)) {
                float tq = bfly16(Q * s1);
                Q = fmaf(v, tq, Q * s0);
            }
            float u = bfly16(Q * ea);
            acc += (double)logf(u);
        }
        acc += (double)(kBlkSteps * E) * LN2;

        if (blk == kNBlks - 1) {
            float u = bfly16(Q * __ldcg(&g_es0_fin[b]));
            acc += (double)logf(u) + (double)E * LN2;
        }
        if (tid == 0) g_part[blk] = acc;
    }

    gbar(2, kGrid);  // partials ready

    // ---- Phase 5: reduce (block 0) ----
    if (blk == 0) {
        if (tid < 128) red[tid] = __ldcg(&g_part[tid]);
        __syncthreads();
#pragma unroll
        for (int s = 64; s > 0; s >>= 1) {
            if (tid < s) red[tid] += red[tid + s];
            __syncthreads();
        }
        if (tid == 0) out[0] = (float)red[0];
    }
}

extern "C" void kernel_launch(void* const* d_in, const int* in_sizes, int n_in,
                              void* d_out, int out_size) {
    const float* s_i = (const float*)d_in[0];
    const float* Wa  = (const float*)d_in[1];
    const float* Wsp = (const float*)d_in[2];
    const float* Wst = (const float*)d_in[3];
    const void*  act = d_in[4];

    cudaFuncSetAttribute(fused_kernel,
                         cudaFuncAttributeMaxDynamicSharedMemorySize,
                         kSmemBytes);
    fused_kernel<<<kGrid, kThreads, kSmemBytes>>>(s_i, Wa, Wsp, Wst, act,
                                                  (float*)d_out);
}